// round 4
// baseline (speedup 1.0000x reference)
#include <cuda_runtime.h>

#define L_TOK 3120
#define DIM 1536
#define NH 12
#define HD 128
#define FR 1560
#define SCALE_F 0.08838834764831845f

// ---------------- scratch ----------------
__device__ float g_q[L_TOK * DIM];           // Q fp32 from GEMM -> tf32+kperm after rms_rope
__device__ float g_k[L_TOK * DIM];
__device__ float g_v[L_TOK * DIM];           // V^T [DIM][L_TOK], j-perm, tf32
__device__ float g_a[L_TOK * DIM];           // attn out, tf32, k-perm
__device__ float g_xt[L_TOK * DIM];          // x tf32, k-perm
__device__ float g_wqkv[3 * DIM * DIM];      // [4608][1536] = [wq^T;wk^T;wv^T] tf32 k-perm
__device__ float g_wo[DIM * DIM];            // wo^T [1536][1536] tf32 k-perm

// ---------------- helpers ----------------
__device__ __forceinline__ unsigned f2tf32(float x) {
  unsigned r; asm("cvt.rna.tf32.f32 %0, %1;" : "=r"(r) : "f"(x)); return r;
}
__device__ __forceinline__ float rnd_tf32(float x) { return __uint_as_float(f2tf32(x)); }
__device__ __forceinline__ void mma_tf32(float c[4], const unsigned a[4],
                                         const unsigned b[2]) {
  asm volatile(
      "mma.sync.aligned.m16n8k8.row.col.f32.tf32.tf32.f32 "
      "{%0,%1,%2,%3},{%4,%5,%6,%7},{%8,%9},{%0,%1,%2,%3};"
      : "+f"(c[0]), "+f"(c[1]), "+f"(c[2]), "+f"(c[3])
      : "r"(a[0]), "r"(a[1]), "r"(a[2]), "r"(a[3]), "r"(b[0]), "r"(b[1]));
}
__device__ __forceinline__ int perm8(int m) { return (m < 4) ? 2 * m : 2 * m - 7; }

// ---------------- cvt x: tf32 round + k-perm within 8 ----------------
__global__ __launch_bounds__(256) void cvt_x_kernel(const float* __restrict__ s,
                                                    float* __restrict__ d, int n8) {
  int i = blockIdx.x * 256 + threadIdx.x;
  if (i < n8) {
    const float4* sp = (const float4*)(s + 8 * (size_t)i);
    float4 a = sp[0], b = sp[1];
    float4 o0 = make_float4(rnd_tf32(a.x), rnd_tf32(b.x), rnd_tf32(a.y), rnd_tf32(b.y));
    float4 o1 = make_float4(rnd_tf32(a.z), rnd_tf32(b.z), rnd_tf32(a.w), rnd_tf32(b.w));
    float4* dp = (float4*)(d + 8 * (size_t)i);
    dp[0] = o0; dp[1] = o1;
  }
}

// ---------------- cvt weights: transpose [K][N]->[N][Kperm] + tf32 ----------------
__global__ __launch_bounds__(256) void cvt_w_kernel(
    const float* __restrict__ w0, const float* __restrict__ w1,
    const float* __restrict__ w2, const float* __restrict__ w3,
    float* __restrict__ qkv, float* __restrict__ wot) {
  __shared__ float tile[32][33];
  const int z = blockIdx.z;
  const float* src = (z == 0) ? w0 : (z == 1) ? w1 : (z == 2) ? w2 : w3;
  float* dst = (z == 3) ? wot : (qkv + (size_t)z * DIM * DIM);
  const int k0 = blockIdx.x * 32, n0 = blockIdx.y * 32;
  const int x = threadIdx.x, y = threadIdx.y;
#pragma unroll
  for (int i = 0; i < 4; i++)
    tile[y + 8 * i][x] = src[(size_t)(k0 + y + 8 * i) * DIM + n0 + x];
  __syncthreads();
  const int kp = k0 + (x & ~7) + perm8(x & 7);
#pragma unroll
  for (int i = 0; i < 4; i++)
    dst[(size_t)(n0 + y + 8 * i) * DIM + kp] = rnd_tf32(tile[x][y + 8 * i]);
}

// ---------------- GEMM: A[M][K] (kperm) @ Wt[N][K] (kperm) ----------------
// QKV=1: N=4608, part epilogues (Q,K fp32 plain; V transposed j-perm tf32)
// QKV=0: N=1536, plain fp32 + bias to C0
#define BK 32
#define TST 40
#define GEMM_SMEM (2 * (128 * TST + 128 * TST) * 4)

template <int QKV>
__global__ __launch_bounds__(256) void gemm_tcA(
    const float* __restrict__ A, const float* __restrict__ Wt,
    const float* __restrict__ b0, const float* __restrict__ b1,
    const float* __restrict__ b2, float* __restrict__ C0,
    float* __restrict__ C1, float* __restrict__ C2, int M) {
  extern __shared__ float smn[];
  float* As = smn;                     // [2][128][40]
  float* Bs = smn + 2 * 128 * TST;     // [2][128][40]

  const int t = threadIdx.x;
  const int m0 = blockIdx.y * 128;
  const int n0 = blockIdx.x * 128;
  const int warp = t >> 5, lane = t & 31;
  const int wm = (warp & 3) * 32;
  const int wn = (warp >> 2) * 64;
  const int g = lane >> 2, t4 = lane & 3;

  float c[2][8][4];
#pragma unroll
  for (int i = 0; i < 2; i++)
#pragma unroll
    for (int j = 0; j < 8; j++)
#pragma unroll
      for (int r = 0; r < 4; r++) c[i][j][r] = 0.f;

  auto prefetch = [&](int buf, int k0) {
    float* asb = As + buf * 128 * TST;
    float* bsb = Bs + buf * 128 * TST;
#pragma unroll
    for (int i = 0; i < 4; i++) {
      int idx = t + 256 * i;
      int row = idx >> 3, c4 = (idx & 7) << 2;
      int gr = m0 + row;
      if (gr >= M) gr = M - 1;
      unsigned dst = (unsigned)__cvta_generic_to_shared(asb + row * TST + c4);
      asm volatile("cp.async.cg.shared.global [%0], [%1], 16;" ::"r"(dst),
                   "l"(A + (size_t)gr * DIM + k0 + c4));
    }
#pragma unroll
    for (int i = 0; i < 4; i++) {
      int idx = t + 256 * i;
      int row = idx >> 3, c4 = (idx & 7) << 2;
      unsigned dst = (unsigned)__cvta_generic_to_shared(bsb + row * TST + c4);
      asm volatile("cp.async.cg.shared.global [%0], [%1], 16;" ::"r"(dst),
                   "l"(Wt + (size_t)(n0 + row) * DIM + k0 + c4));
    }
  };

  prefetch(0, 0);
  asm volatile("cp.async.commit_group;");

  const int KT = DIM / BK;
  for (int kt = 0; kt < KT; kt++) {
    const int buf = kt & 1;
    if (kt + 1 < KT) prefetch(buf ^ 1, (kt + 1) * BK);
    asm volatile("cp.async.commit_group;");
    asm volatile("cp.async.wait_group 1;");
    __syncthreads();

    const float* asb = As + buf * 128 * TST;
    const float* bsb = Bs + buf * 128 * TST;

#pragma unroll
    for (int ka = 0; ka < 4; ka++) {
      const int kk = ka * 8 + 2 * t4;
      unsigned av[2][4], bv[8][2];
#pragma unroll
      for (int am = 0; am < 2; am++) {
        const int r = wm + 16 * am + g;
        float2 lo = *(const float2*)(asb + r * TST + kk);
        float2 hi = *(const float2*)(asb + (r + 8) * TST + kk);
        av[am][0] = __float_as_uint(lo.x); av[am][1] = __float_as_uint(hi.x);
        av[am][2] = __float_as_uint(lo.y); av[am][3] = __float_as_uint(hi.y);
      }
#pragma unroll
      for (int an = 0; an < 8; an++) {
        const int cn = wn + 8 * an + g;
        float2 bb = *(const float2*)(bsb + cn * TST + kk);
        bv[an][0] = __float_as_uint(bb.x); bv[an][1] = __float_as_uint(bb.y);
      }
#pragma unroll
      for (int am = 0; am < 2; am++)
#pragma unroll
        for (int an = 0; an < 8; an++) mma_tf32(c[am][an], av[am], bv[an]);
    }
    __syncthreads();
  }

  // ---- epilogue ----
  int part = 0;
  const float* bias = b0;
  float* C = C0;
  int ncol0 = n0;
  if (QKV) {
    part = n0 / DIM;
    ncol0 = n0 - part * DIM;
    bias = (part == 0) ? b0 : (part == 1) ? b1 : b2;
    C = (part == 0) ? C0 : (part == 1) ? C1 : C2;
  }
#pragma unroll
  for (int am = 0; am < 2; am++) {
    const int r0 = m0 + wm + 16 * am + g;
    const int r1 = r0 + 8;
#pragma unroll
    for (int an = 0; an < 8; an++) {
      const int col = ncol0 + wn + 8 * an + 2 * t4;
      const float bb0 = bias[col], bb1 = bias[col + 1];
      if (QKV && part == 2) {
        if (r0 < M) {
          int jp = (r0 & ~7) | perm8(r0 & 7);
          C[(size_t)col * L_TOK + jp] = rnd_tf32(c[am][an][0] + bb0);
          C[(size_t)(col + 1) * L_TOK + jp] = rnd_tf32(c[am][an][1] + bb1);
        }
        if (r1 < M) {
          int jp = (r1 & ~7) | perm8(r1 & 7);
          C[(size_t)col * L_TOK + jp] = rnd_tf32(c[am][an][2] + bb0);
          C[(size_t)(col + 1) * L_TOK + jp] = rnd_tf32(c[am][an][3] + bb1);
        }
      } else {
        if (r0 < M) {
          float2 v0 = make_float2(c[am][an][0] + bb0, c[am][an][1] + bb1);
          *(float2*)(C + (size_t)r0 * DIM + col) = v0;
        }
        if (r1 < M) {
          float2 v1 = make_float2(c[am][an][2] + bb0, c[am][an][3] + bb1);
          *(float2*)(C + (size_t)r1 * DIM + col) = v1;
        }
      }
    }
  }
}

// ---------------- fused RMSNorm + RoPE + tf32 + k-perm store ----------------
__global__ __launch_bounds__(256) void rms_rope_kernel(
    float* __restrict__ qbuf, float* __restrict__ kbuf,
    const float* __restrict__ gq, const float* __restrict__ gk,
    const float* __restrict__ cosp, const float* __restrict__ sinp) {
  const int l = blockIdx.x;
  float* row = (blockIdx.y == 0) ? (qbuf + (size_t)l * DIM) : (kbuf + (size_t)l * DIM);
  const float* g = (blockIdx.y == 0) ? gq : gk;
  const int t = threadIdx.x;

  float2 v[3];
  float ss = 0.f;
#pragma unroll
  for (int j = 0; j < 3; j++) {
    int p = t + 256 * j;
    v[j] = ((const float2*)row)[p];
    ss += v[j].x * v[j].x + v[j].y * v[j].y;
  }
#pragma unroll
  for (int off = 16; off > 0; off >>= 1)
    ss += __shfl_xor_sync(0xffffffffu, ss, off);
  __shared__ float red[8];
  if ((t & 31) == 0) red[t >> 5] = ss;
  __syncthreads();
  float tot = 0.f;
#pragma unroll
  for (int w = 0; w < 8; w++) tot += red[w];
  const float r = rsqrtf(tot * (1.0f / (float)DIM) + 1e-6f);

#pragma unroll
  for (int j = 0; j < 3; j++) {
    int p = t + 256 * j;
    int hd2 = p & 63;
    float cth = cosp[l * 64 + hd2];
    float sth = sinp[l * 64 + hd2];
    float e = v[j].x * r * g[2 * p];
    float o = v[j].y * r * g[2 * p + 1];
    int d0 = 2 * p;
    int base = d0 & ~7;
    int m0 = d0 & 7;
    row[base + perm8(m0)] = rnd_tf32(e * cth - o * sth);
    row[base + perm8(m0 + 1)] = rnd_tf32(e * sth + o * cth);
  }
}

// ---------------- tensor-core flash attention ----------------
#define ATT_SMEM_F (8448 + 8704 + 4352 + 64 + 64 + 128 + 128)
#define ATT_SMEM (ATT_SMEM_F * 4)

__global__ __launch_bounds__(128, 2) void attn_tc_kernel(
    const float* __restrict__ q, const float* __restrict__ k,
    const float* __restrict__ vt, float* __restrict__ o) {
  extern __shared__ float sm[];
  float* Qs = sm;                 // [64][132]
  float* KVs = sm + 8448;         // K [64][132] then Vt [128][68]
  float* Ps = KVs + 8704;         // [64][68]
  float* m_s = Ps + 4352;
  float* l_s = m_s + 64;
  float* red_m = l_s + 64;        // [64][2]
  float* red_l = red_m + 128;     // [64][2]

  const int t = threadIdx.x, lane = t & 31, warp = t >> 5;
  const int g = lane >> 2, t4 = lane & 3;
  const int wr = warp & 1, wc = warp >> 1;
  const int q0 = blockIdx.x * 64, h = blockIdx.y;
  const int r0l = wr * 32 + g;

#pragma unroll
  for (int i = 0; i < 16; i++) {
    int idx = t + 128 * i, r = idx >> 5, c4 = (idx & 31) << 2;
    int qr = q0 + r;
    int sz = (qr < L_TOK) ? 16 : 0;
    if (qr >= L_TOK) qr = L_TOK - 1;
    unsigned dst = (unsigned)__cvta_generic_to_shared(Qs + r * 132 + c4);
    asm volatile("cp.async.cg.shared.global [%0], [%1], 16, %2;" ::"r"(dst),
                 "l"(q + (size_t)qr * DIM + h * HD + c4), "r"(sz));
  }
  asm volatile("cp.async.commit_group;");
  if (t < 64) { m_s[t] = -3.0e38f; l_s[t] = 0.f; }

  float oa[2][8][4];
#pragma unroll
  for (int m = 0; m < 2; m++)
#pragma unroll
    for (int a = 0; a < 8; a++)
#pragma unroll
      for (int r = 0; r < 4; r++) oa[m][a][r] = 0.f;

  int km[2][2];
#pragma unroll
  for (int m = 0; m < 2; m++)
#pragma unroll
    for (int hf = 0; hf < 2; hf++) {
      int grow = q0 + r0l + 16 * m + 8 * hf;
      km[m][hf] = (grow < FR) ? FR : L_TOK;
    }

  int qlast = q0 + 63; if (qlast >= L_TOK) qlast = L_TOK - 1;
  const int ntiles = (((qlast < FR) ? FR : L_TOK) + 63) >> 6;

  for (int kt = 0; kt < ntiles; kt++) {
    const int kb = kt * 64;
    __syncthreads();
#pragma unroll
    for (int i = 0; i < 16; i++) {
      int idx = t + 128 * i, r = idx >> 5, c4 = (idx & 31) << 2;
      int kr = kb + r;
      int sz = (kr < L_TOK) ? 16 : 0;
      if (kr >= L_TOK) kr = L_TOK - 1;
      unsigned dst = (unsigned)__cvta_generic_to_shared(KVs + r * 132 + c4);
      asm volatile("cp.async.cg.shared.global [%0], [%1], 16, %2;" ::"r"(dst),
                   "l"(k + (size_t)kr * DIM + h * HD + c4), "r"(sz));
    }
    asm volatile("cp.async.commit_group;");
    asm volatile("cp.async.wait_group 0;");
    __syncthreads();

    float s_[2][4][4];
#pragma unroll
    for (int m = 0; m < 2; m++)
#pragma unroll
      for (int a = 0; a < 4; a++)
#pragma unroll
        for (int r = 0; r < 4; r++) s_[m][a][r] = 0.f;

#pragma unroll
    for (int k8 = 0; k8 < 16; k8++) {
      unsigned av[2][4];
#pragma unroll
      for (int m = 0; m < 2; m++) {
        float2 x0 = *(const float2*)(Qs + (wr * 32 + m * 16 + g) * 132 + k8 * 8 + 2 * t4);
        float2 x1 = *(const float2*)(Qs + (wr * 32 + m * 16 + g + 8) * 132 + k8 * 8 + 2 * t4);
        av[m][0] = __float_as_uint(x0.x); av[m][1] = __float_as_uint(x1.x);
        av[m][2] = __float_as_uint(x0.y); av[m][3] = __float_as_uint(x1.y);
      }
#pragma unroll
      for (int a = 0; a < 4; a++) {
        float2 kv = *(const float2*)(KVs + (wc * 32 + a * 8 + g) * 132 + k8 * 8 + 2 * t4);
        unsigned bv[2] = {__float_as_uint(kv.x), __float_as_uint(kv.y)};
        mma_tf32(s_[0][a], av[0], bv);
        mma_tf32(s_[1][a], av[1], bv);
      }
    }

#pragma unroll
    for (int m = 0; m < 2; m++)
#pragma unroll
      for (int a = 0; a < 4; a++) {
        int cb = kb + wc * 32 + a * 8 + 2 * t4;
        s_[m][a][0] = (cb     < km[m][0]) ? s_[m][a][0] * SCALE_F : -3.0e38f;
        s_[m][a][1] = (cb + 1 < km[m][0]) ? s_[m][a][1] * SCALE_F : -3.0e38f;
        s_[m][a][2] = (cb     < km[m][1]) ? s_[m][a][2] * SCALE_F : -3.0e38f;
        s_[m][a][3] = (cb + 1 < km[m][1]) ? s_[m][a][3] * SCALE_F : -3.0e38f;
      }

    float pm[2][2];
#pragma unroll
    for (int m = 0; m < 2; m++) { pm[m][0] = -3.0e38f; pm[m][1] = -3.0e38f; }
#pragma unroll
    for (int m = 0; m < 2; m++)
#pragma unroll
      for (int a = 0; a < 4; a++) {
        pm[m][0] = fmaxf(pm[m][0], fmaxf(s_[m][a][0], s_[m][a][1]));
        pm[m][1] = fmaxf(pm[m][1], fmaxf(s_[m][a][2], s_[m][a][3]));
      }
#pragma unroll
    for (int m = 0; m < 2; m++)
#pragma unroll
      for (int hf = 0; hf < 2; hf++) {
        pm[m][hf] = fmaxf(pm[m][hf], __shfl_xor_sync(0xffffffffu, pm[m][hf], 1));
        pm[m][hf] = fmaxf(pm[m][hf], __shfl_xor_sync(0xffffffffu, pm[m][hf], 2));
      }
    if (t4 == 0) {
#pragma unroll
      for (int m = 0; m < 2; m++)
#pragma unroll
        for (int hf = 0; hf < 2; hf++)
          red_m[(r0l + 16 * m + 8 * hf) * 2 + wc] = pm[m][hf];
    }
    __syncthreads();

#pragma unroll
    for (int i = 0; i < 16; i++) {
      int idx = t + 128 * i, d = idx >> 4, cq = (idx & 15) << 2;
      int jj = kb + cq;
      int sz = (jj < L_TOK) ? 16 : 0;
      if (jj >= L_TOK) jj = L_TOK - 4;
      unsigned dst = (unsigned)__cvta_generic_to_shared(KVs + d * 68 + cq);
      asm volatile("cp.async.cg.shared.global [%0], [%1], 16, %2;" ::"r"(dst),
                   "l"(vt + (size_t)(h * HD + d) * L_TOK + jj), "r"(sz));
    }
    asm volatile("cp.async.commit_group;");

    float mnew[2][2], corr[2][2];
#pragma unroll
    for (int m = 0; m < 2; m++)
#pragma unroll
      for (int hf = 0; hf < 2; hf++) {
        int rl = r0l + 16 * m + 8 * hf;
        float mold = m_s[rl];
        float mn = fmaxf(mold, fmaxf(red_m[rl * 2], red_m[rl * 2 + 1]));
        mnew[m][hf] = mn;
        corr[m][hf] = __expf(mold - mn);
      }
    float pl[2][2] = {{0.f, 0.f}, {0.f, 0.f}};
    const int p0pos = (t4 < 2) ? 4 * t4 : 4 * t4 - 7;
    const int p1pos = (t4 < 2) ? 4 * t4 + 2 : 4 * t4 - 5;
#pragma unroll
    for (int m = 0; m < 2; m++) {
      int rl0 = r0l + 16 * m;
#pragma unroll
      for (int a = 0; a < 4; a++) {
        int cp0 = wc * 32 + a * 8;
        float e0 = __expf(s_[m][a][0] - mnew[m][0]);
        float e1 = __expf(s_[m][a][1] - mnew[m][0]);
        float e2 = __expf(s_[m][a][2] - mnew[m][1]);
        float e3 = __expf(s_[m][a][3] - mnew[m][1]);
        pl[m][0] += e0 + e1;
        pl[m][1] += e2 + e3;
        Ps[rl0 * 68 + cp0 + p0pos] = rnd_tf32(e0);
        Ps[rl0 * 68 + cp0 + p1pos] = rnd_tf32(e1);
        Ps[(rl0 + 8) * 68 + cp0 + p0pos] = rnd_tf32(e2);
        Ps[(rl0 + 8) * 68 + cp0 + p1pos] = rnd_tf32(e3);
      }
    }
#pragma unroll
    for (int m = 0; m < 2; m++)
#pragma unroll
      for (int hf = 0; hf < 2; hf++) {
        pl[m][hf] += __shfl_xor_sync(0xffffffffu, pl[m][hf], 1);
        pl[m][hf] += __shfl_xor_sync(0xffffffffu, pl[m][hf], 2);
      }
    if (t4 == 0) {
#pragma unroll
      for (int m = 0; m < 2; m++)
#pragma unroll
        for (int hf = 0; hf < 2; hf++)
          red_l[(r0l + 16 * m + 8 * hf) * 2 + wc] = pl[m][hf];
    }
    __syncthreads();
    if (wc == 0 && t4 == 0) {
#pragma unroll
      for (int m = 0; m < 2; m++)
#pragma unroll
        for (int hf = 0; hf < 2; hf++) {
          int rl = r0l + 16 * m + 8 * hf;
          l_s[rl] = l_s[rl] * corr[m][hf] + red_l[rl * 2] + red_l[rl * 2 + 1];
          m_s[rl] = mnew[m][hf];
        }
    }
#pragma unroll
    for (int m = 0; m < 2; m++)
#pragma unroll
      for (int a = 0; a < 8; a++) {
        oa[m][a][0] *= corr[m][0]; oa[m][a][1] *= corr[m][0];
        oa[m][a][2] *= corr[m][1]; oa[m][a][3] *= corr[m][1];
      }
    asm volatile("cp.async.wait_group 0;");
    __syncthreads();

#pragma unroll
    for (int k8 = 0; k8 < 8; k8++) {
      unsigned av[2][4];
#pragma unroll
      for (int m = 0; m < 2; m++) {
        float2 p0 = *(const float2*)(Ps + (wr * 32 + 16 * m + g) * 68 + k8 * 8 + 2 * t4);
        float2 p1 = *(const float2*)(Ps + (wr * 32 + 16 * m + g + 8) * 68 + k8 * 8 + 2 * t4);
        av[m][0] = __float_as_uint(p0.x); av[m][1] = __float_as_uint(p1.x);
        av[m][2] = __float_as_uint(p0.y); av[m][3] = __float_as_uint(p1.y);
      }
#pragma unroll
      for (int a = 0; a < 8; a++) {
        float2 vv = *(const float2*)(KVs + (wc * 64 + a * 8 + g) * 68 + k8 * 8 + 2 * t4);
        unsigned bv[2] = {__float_as_uint(vv.x), __float_as_uint(vv.y)};
        mma_tf32(oa[0][a], av[0], bv);
        mma_tf32(oa[1][a], av[1], bv);
      }
    }
  }
  __syncthreads();

  // epilogue: /l, tf32 round, k-perm store (feeds O-projection GEMM)
  const int p0pos = (t4 < 2) ? 4 * t4 : 4 * t4 - 7;
  const int p1pos = (t4 < 2) ? 4 * t4 + 2 : 4 * t4 - 5;
#pragma unroll
  for (int m = 0; m < 2; m++)
#pragma unroll
    for (int hf = 0; hf < 2; hf++) {
      int rl = r0l + 16 * m + 8 * hf;
      int grow = q0 + rl;
      if (grow < L_TOK) {
        float inv = 1.0f / l_s[rl];
#pragma unroll
        for (int a = 0; a < 8; a++) {
          int colbase = h * HD + wc * 64 + a * 8;
          o[(size_t)grow * DIM + colbase + p0pos] = rnd_tf32(oa[m][a][hf * 2] * inv);
          o[(size_t)grow * DIM + colbase + p1pos] = rnd_tf32(oa[m][a][hf * 2 + 1] * inv);
        }
      }
    }
}

// ---------------- launch ----------------
extern "C" void kernel_launch(void* const* d_in, const int* in_sizes, int n_in,
                              void* d_out, int out_size) {
  const float* x  = (const float*)d_in[0];
  const float* wq = (const float*)d_in[1];
  const float* wk = (const float*)d_in[2];
  const float* wv = (const float*)d_in[3];
  const float* wo = (const float*)d_in[4];
  const float* bq = (const float*)d_in[5];
  const float* bk = (const float*)d_in[6];
  const float* bv = (const float*)d_in[7];
  const float* bo = (const float*)d_in[8];
  const float* gq = (const float*)d_in[9];
  const float* gk = (const float*)d_in[10];
  const float* fc = (const float*)d_in[11];
  const float* fs = (const float*)d_in[12];
  float* out = (float*)d_out;

  float *qb, *kb, *vb, *ab, *xt, *wqkv, *wot;
  cudaGetSymbolAddress((void**)&qb, g_q);
  cudaGetSymbolAddress((void**)&kb, g_k);
  cudaGetSymbolAddress((void**)&vb, g_v);
  cudaGetSymbolAddress((void**)&ab, g_a);
  cudaGetSymbolAddress((void**)&xt, g_xt);
  cudaGetSymbolAddress((void**)&wqkv, g_wqkv);
  cudaGetSymbolAddress((void**)&wot, g_wo);

  cudaFuncSetAttribute(gemm_tcA<0>, cudaFuncAttributeMaxDynamicSharedMemorySize, GEMM_SMEM);
  cudaFuncSetAttribute(gemm_tcA<1>, cudaFuncAttributeMaxDynamicSharedMemorySize, GEMM_SMEM);
  cudaFuncSetAttribute(attn_tc_kernel, cudaFuncAttributeMaxDynamicSharedMemorySize, ATT_SMEM);

  int nx8 = L_TOK * DIM / 8;
  cvt_x_kernel<<<(nx8 + 255) / 256, 256>>>(x, xt, nx8);
  cvt_w_kernel<<<dim3(DIM / 32, DIM / 32, 4), dim3(32, 8)>>>(wq, wk, wv, wo, wqkv, wot);

  gemm_tcA<1><<<dim3(3 * DIM / 128, (L_TOK + 127) / 128), 256, GEMM_SMEM>>>(
      xt, wqkv, bq, bk, bv, qb, kb, vb, L_TOK);

  rms_rope_kernel<<<dim3(L_TOK, 2), 256>>>(qb, kb, gq, gk, fc, fs);

  attn_tc_kernel<<<dim3((L_TOK + 63) / 64, NH), 128, ATT_SMEM>>>(qb, kb, vb, ab);

  gemm_tcA<0><<<dim3(DIM / 128, (L_TOK + 127) / 128), 256, GEMM_SMEM>>>(
      ab, wot, bo, nullptr, nullptr, out, nullptr, nullptr, L_TOK);
}

// round 6
// speedup vs baseline: 1.9570x; 1.9570x over previous
#include <cuda_runtime.h>
#include <cuda_fp16.h>
#include <cstdint>

#define L_TOK 3120
#define DIM 1536
#define NH 12
#define HD 128
#define FR 1560
#define SCALE_F 0.08838834764831845f

// ---------------- scratch ----------------
__device__ __align__(16) __half g_q[L_TOK * DIM];       // Q fp16 (post rms_rope)
__device__ __align__(16) __half g_k[L_TOK * DIM];
__device__ __align__(16) __half g_v[L_TOK * DIM];       // V^T [DIM][L_TOK] fp16
__device__ __align__(16) __half g_a[L_TOK * DIM];       // attn out fp16
__device__ __align__(16) __half g_xh[L_TOK * DIM];      // x fp16
__device__ __align__(16) __half g_wqkv[3 * DIM * DIM];  // [4608][1536] fp16 (W^T)
__device__ __align__(16) __half g_wo[DIM * DIM];        // wo^T fp16

// ---------------- helpers ----------------
__device__ __forceinline__ void mma_f16(float c[4], const unsigned a[4],
                                        const unsigned* b) {
  asm volatile(
      "mma.sync.aligned.m16n8k16.row.col.f32.f16.f16.f32 "
      "{%0,%1,%2,%3},{%4,%5,%6,%7},{%8,%9},{%0,%1,%2,%3};"
      : "+f"(c[0]), "+f"(c[1]), "+f"(c[2]), "+f"(c[3])
      : "r"(a[0]), "r"(a[1]), "r"(a[2]), "r"(a[3]), "r"(b[0]), "r"(b[1]));
}
__device__ __forceinline__ void ldsm4(unsigned r[4], uint32_t addr) {
  asm volatile(
      "ldmatrix.sync.aligned.m8n8.x4.shared.b16 {%0,%1,%2,%3}, [%4];"
      : "=r"(r[0]), "=r"(r[1]), "=r"(r[2]), "=r"(r[3]) : "r"(addr));
}
__device__ __forceinline__ uint32_t smem_u32(const void* p) {
  uint32_t a;
  asm("{ .reg .u64 t; cvta.to.shared.u64 t, %1; cvt.u32.u64 %0, t; }"
      : "=r"(a) : "l"(p));
  return a;
}

// ---------------- cvt kernels ----------------
__global__ __launch_bounds__(256) void cvt_x_kernel(const float* __restrict__ s,
                                                    __half* __restrict__ d, int n4) {
  int i = blockIdx.x * 256 + threadIdx.x;
  if (i < n4) {
    float4 v = *(const float4*)(s + 4 * (size_t)i);
    __half2* dp = (__half2*)(d + 4 * (size_t)i);
    dp[0] = __floats2half2_rn(v.x, v.y);
    dp[1] = __floats2half2_rn(v.z, v.w);
  }
}

__global__ __launch_bounds__(256) void cvt_w_kernel(
    const float* __restrict__ w0, const float* __restrict__ w1,
    const float* __restrict__ w2, const float* __restrict__ w3,
    __half* __restrict__ qkv, __half* __restrict__ wot) {
  __shared__ float tile[32][33];
  const int z = blockIdx.z;
  const float* src = (z == 0) ? w0 : (z == 1) ? w1 : (z == 2) ? w2 : w3;
  __half* dst = (z == 3) ? wot : (qkv + (size_t)z * DIM * DIM);
  const int k0 = blockIdx.x * 32, n0 = blockIdx.y * 32;
  const int x = threadIdx.x, y = threadIdx.y;
#pragma unroll
  for (int i = 0; i < 4; i++)
    tile[y + 8 * i][x] = src[(size_t)(k0 + y + 8 * i) * DIM + n0 + x];
  __syncthreads();
#pragma unroll
  for (int i = 0; i < 4; i++)
    dst[(size_t)(n0 + y + 8 * i) * DIM + k0 + x] = __float2half(tile[x][y + 8 * i]);
}

// ---------------- fp16 GEMM: C[M][N] = A[M][K] @ Wt[N][K]^T ----------------
// CTA 128x128, BK=32, 256 thr, warp 32x64. ldmatrix + m16n8k16.
#define AST 40  // halfs; 80B stride -> conflict-free LDSM
#define GEMM_SMEM (2 * (128 * AST + 128 * AST) * 2)

template <int QKV>
__global__ __launch_bounds__(256) void gemm_f16(
    const __half* __restrict__ A, const __half* __restrict__ Wt,
    const float* __restrict__ b0, const float* __restrict__ b1,
    const float* __restrict__ b2, float* __restrict__ Cf,
    __half* __restrict__ H0, __half* __restrict__ H1,
    __half* __restrict__ H2, int M) {
  extern __shared__ __half smh[];
  __half* As = smh;                       // [2][128][40]
  __half* Bs = smh + 2 * 128 * AST;       // [2][128][40]
  const uint32_t as_u = smem_u32(As), bs_u = smem_u32(Bs);

  const int t = threadIdx.x;
  const int m0 = blockIdx.y * 128;
  const int n0g = blockIdx.x * 128;
  const int warp = t >> 5, lane = t & 31;
  const int wm = (warp & 3) * 32;
  const int wn = (warp >> 2) * 64;
  const int g = lane >> 2, t4 = lane & 3;
  const int ar = lane & 15, aklo = (lane & 16) >> 1;         // A ldsm addr parts
  const int br = (lane & 7) + ((lane & 16) >> 1), bklo = lane & 8;

  float c[2][8][4];
#pragma unroll
  for (int i = 0; i < 2; i++)
#pragma unroll
    for (int j = 0; j < 8; j++)
#pragma unroll
      for (int r = 0; r < 4; r++) c[i][j][r] = 0.f;

  auto prefetch = [&](int buf, int k0) {
    __half* asb = As + buf * 128 * AST;
    __half* bsb = Bs + buf * 128 * AST;
#pragma unroll
    for (int i = 0; i < 2; i++) {
      int idx = t + 256 * i;                    // 512 chunks of 8 halfs (A)
      int row = idx >> 2, c8 = (idx & 3) << 3;
      int gr = m0 + row;
      if (gr >= M) gr = M - 1;
      unsigned dst = (unsigned)__cvta_generic_to_shared(asb + row * AST + c8);
      asm volatile("cp.async.cg.shared.global [%0], [%1], 16;" ::"r"(dst),
                   "l"(A + (size_t)gr * DIM + k0 + c8));
    }
#pragma unroll
    for (int i = 0; i < 2; i++) {
      int idx = t + 256 * i;
      int row = idx >> 2, c8 = (idx & 3) << 3;
      unsigned dst = (unsigned)__cvta_generic_to_shared(bsb + row * AST + c8);
      asm volatile("cp.async.cg.shared.global [%0], [%1], 16;" ::"r"(dst),
                   "l"(Wt + (size_t)(n0g + row) * DIM + k0 + c8));
    }
  };

  prefetch(0, 0);
  asm volatile("cp.async.commit_group;");

  const int KT = DIM / 32;
  for (int kt = 0; kt < KT; kt++) {
    const int buf = kt & 1;
    if (kt + 1 < KT) prefetch(buf ^ 1, (kt + 1) * 32);
    asm volatile("cp.async.commit_group;");
    asm volatile("cp.async.wait_group 1;");
    __syncthreads();

    const uint32_t au = as_u + buf * 128 * AST * 2;
    const uint32_t bu = bs_u + buf * 128 * AST * 2;

#pragma unroll
    for (int kk = 0; kk < 32; kk += 16) {
      unsigned av[2][4], bv[4][4];
#pragma unroll
      for (int am = 0; am < 2; am++)
        ldsm4(av[am], au + ((wm + 16 * am + ar) * AST + kk + aklo) * 2);
#pragma unroll
      for (int bn = 0; bn < 4; bn++)
        ldsm4(bv[bn], bu + ((wn + 16 * bn + br) * AST + kk + bklo) * 2);
#pragma unroll
      for (int am = 0; am < 2; am++)
#pragma unroll
        for (int an = 0; an < 8; an++)
          mma_f16(c[am][an], av[am], (an & 1) ? (bv[an >> 1] + 2) : bv[an >> 1]);
    }
    __syncthreads();
  }

  // ---- epilogue ----
  int part = 0, ncol0 = n0g;
  const float* bias = b0;
  if (QKV) {
    part = n0g / DIM;
    ncol0 = n0g - part * DIM;
    bias = (part == 0) ? b0 : (part == 1) ? b1 : b2;
  }
#pragma unroll
  for (int am = 0; am < 2; am++) {
    const int r0 = m0 + wm + 16 * am + g;
    const int r1 = r0 + 8;
#pragma unroll
    for (int an = 0; an < 8; an++) {
      const int col = ncol0 + wn + 8 * an + 2 * t4;
      const float bb0 = bias[col], bb1 = bias[col + 1];
      if (!QKV) {
        if (r0 < M)
          *(float2*)(Cf + (size_t)r0 * DIM + col) =
              make_float2(c[am][an][0] + bb0, c[am][an][1] + bb1);
        if (r1 < M)
          *(float2*)(Cf + (size_t)r1 * DIM + col) =
              make_float2(c[am][an][2] + bb0, c[am][an][3] + bb1);
      } else if (part == 2) {
        if (r0 < M) {
          H2[(size_t)col * L_TOK + r0] = __float2half(c[am][an][0] + bb0);
          H2[(size_t)(col + 1) * L_TOK + r0] = __float2half(c[am][an][1] + bb1);
        }
        if (r1 < M) {
          H2[(size_t)col * L_TOK + r1] = __float2half(c[am][an][2] + bb0);
          H2[(size_t)(col + 1) * L_TOK + r1] = __float2half(c[am][an][3] + bb1);
        }
      } else {
        __half* H = (part == 0) ? H0 : H1;
        if (r0 < M)
          *(__half2*)(H + (size_t)r0 * DIM + col) =
              __floats2half2_rn(c[am][an][0] + bb0, c[am][an][1] + bb1);
        if (r1 < M)
          *(__half2*)(H + (size_t)r1 * DIM + col) =
              __floats2half2_rn(c[am][an][2] + bb0, c[am][an][3] + bb1);
      }
    }
  }
}

// ---------------- fused RMSNorm + RoPE (fp16 in/out) ----------------
__global__ __launch_bounds__(256) void rms_rope_kernel(
    __half* __restrict__ qbuf, __half* __restrict__ kbuf,
    const float* __restrict__ gq, const float* __restrict__ gk,
    const float* __restrict__ cosp, const float* __restrict__ sinp) {
  const int l = blockIdx.x;
  __half* row = (blockIdx.y == 0) ? (qbuf + (size_t)l * DIM) : (kbuf + (size_t)l * DIM);
  const float* g = (blockIdx.y == 0) ? gq : gk;
  const int t = threadIdx.x;

  float2 v[3];
  float ss = 0.f;
#pragma unroll
  for (int j = 0; j < 3; j++) {
    int p = t + 256 * j;
    v[j] = __half22float2(((const __half2*)row)[p]);
    ss += v[j].x * v[j].x + v[j].y * v[j].y;
  }
#pragma unroll
  for (int off = 16; off > 0; off >>= 1)
    ss += __shfl_xor_sync(0xffffffffu, ss, off);
  __shared__ float red[8];
  if ((t & 31) == 0) red[t >> 5] = ss;
  __syncthreads();
  float tot = 0.f;
#pragma unroll
  for (int w = 0; w < 8; w++) tot += red[w];
  const float r = rsqrtf(tot * (1.0f / (float)DIM) + 1e-6f);

#pragma unroll
  for (int j = 0; j < 3; j++) {
    int p = t + 256 * j;
    int hd2 = p & 63;
    float cth = cosp[l * 64 + hd2];
    float sth = sinp[l * 64 + hd2];
    float e = v[j].x * r * g[2 * p];
    float o = v[j].y * r * g[2 * p + 1];
    ((__half2*)row)[p] = __floats2half2_rn(e * cth - o * sth, e * sth + o * cth);
  }
}

// ---------------- fp16 tensor-core flash attention ----------------
// 128 thr = 4 warps 2x2. BQ=BKV=64. Qs[64][136]h, KV union(K[64][136] / Vt[128][72])h,
// Ps[64][72]h, fp32 softmax state.
#define QS_H (64 * 136)
#define KV_H (128 * 72)          // 9216 >= 64*136=8704
#define PS_H (64 * 72)
#define ATT_SMEM ((QS_H + KV_H + PS_H) * 2 + (64 + 64 + 128 + 128) * 4)

__global__ __launch_bounds__(128, 2) void attn_f16_kernel(
    const __half* __restrict__ q, const __half* __restrict__ k,
    const __half* __restrict__ vt, __half* __restrict__ o) {
  extern __shared__ __half smh[];
  __half* Qs = smh;
  __half* KVs = smh + QS_H;
  __half* Ps = KVs + KV_H;
  float* m_s = (float*)(Ps + PS_H);
  float* l_s = m_s + 64;
  float* red_m = l_s + 64;     // [64][2]
  float* red_l = red_m + 128;  // [64][2]
  const uint32_t qs_u = smem_u32(Qs), kv_u = smem_u32(KVs), ps_u = smem_u32(Ps);

  const int t = threadIdx.x, lane = t & 31, warp = t >> 5;
  const int g = lane >> 2, t4 = lane & 3;
  const int wr = warp & 1, wc = warp >> 1;
  const int q0 = blockIdx.x * 64, h = blockIdx.y;
  const int r0l = wr * 32 + g;
  const int ar = lane & 15, aklo = (lane & 16) >> 1;
  const int br = (lane & 7) + ((lane & 16) >> 1), bklo = lane & 8;

  // ---- Q tile: 64 rows x 128 halfs ----
#pragma unroll
  for (int i = 0; i < 8; i++) {
    int idx = t + 128 * i, r = idx >> 4, c8 = (idx & 15) << 3;
    int qr = q0 + r;
    int sz = (qr < L_TOK) ? 16 : 0;
    if (qr >= L_TOK) qr = L_TOK - 1;
    unsigned dst = (unsigned)__cvta_generic_to_shared(Qs + r * 136 + c8);
    asm volatile("cp.async.cg.shared.global [%0], [%1], 16, %2;" ::"r"(dst),
                 "l"(q + (size_t)qr * DIM + h * HD + c8), "r"(sz));
  }
  asm volatile("cp.async.commit_group;");
  if (t < 64) { m_s[t] = -3.0e38f; l_s[t] = 0.f; }

  float oa[2][8][4];
#pragma unroll
  for (int m = 0; m < 2; m++)
#pragma unroll
    for (int a = 0; a < 8; a++)
#pragma unroll
      for (int r = 0; r < 4; r++) oa[m][a][r] = 0.f;

  int km[2][2];
#pragma unroll
  for (int m = 0; m < 2; m++)
#pragma unroll
    for (int hf = 0; hf < 2; hf++) {
      int grow = q0 + r0l + 16 * m + 8 * hf;
      km[m][hf] = (grow < FR) ? FR : L_TOK;
    }

  int qlast = q0 + 63; if (qlast >= L_TOK) qlast = L_TOK - 1;
  const int ntiles = (((qlast < FR) ? FR : L_TOK) + 63) >> 6;

  for (int kt = 0; kt < ntiles; kt++) {
    const int kb = kt * 64;
    __syncthreads();
    // ---- K tile ----
#pragma unroll
    for (int i = 0; i < 8; i++) {
      int idx = t + 128 * i, r = idx >> 4, c8 = (idx & 15) << 3;
      int kr = kb + r;
      int sz = (kr < L_TOK) ? 16 : 0;
      if (kr >= L_TOK) kr = L_TOK - 1;
      unsigned dst = (unsigned)__cvta_generic_to_shared(KVs + r * 136 + c8);
      asm volatile("cp.async.cg.shared.global [%0], [%1], 16, %2;" ::"r"(dst),
                   "l"(k + (size_t)kr * DIM + h * HD + c8), "r"(sz));
    }
    asm volatile("cp.async.commit_group;");
    asm volatile("cp.async.wait_group 0;");
    __syncthreads();

    // ---- S = Q K^T ----
    float s_[2][4][4];
#pragma unroll
    for (int m = 0; m < 2; m++)
#pragma unroll
      for (int a = 0; a < 4; a++)
#pragma unroll
        for (int r = 0; r < 4; r++) s_[m][a][r] = 0.f;

#pragma unroll
    for (int k16 = 0; k16 < 8; k16++) {
      const int kk = k16 * 16;
      unsigned av[2][4], bv[2][4];
#pragma unroll
      for (int m = 0; m < 2; m++)
        ldsm4(av[m], qs_u + ((wr * 32 + 16 * m + ar) * 136 + kk + aklo) * 2);
#pragma unroll
      for (int bn = 0; bn < 2; bn++)
        ldsm4(bv[bn], kv_u + ((wc * 32 + 16 * bn + br) * 136 + kk + bklo) * 2);
#pragma unroll
      for (int m = 0; m < 2; m++)
#pragma unroll
        for (int a = 0; a < 4; a++)
          mma_f16(s_[m][a], av[m], (a & 1) ? (bv[a >> 1] + 2) : bv[a >> 1]);
    }

    // ---- scale + mask ----
#pragma unroll
    for (int m = 0; m < 2; m++)
#pragma unroll
      for (int a = 0; a < 4; a++) {
        int cb = kb + wc * 32 + a * 8 + 2 * t4;
        s_[m][a][0] = (cb     < km[m][0]) ? s_[m][a][0] * SCALE_F : -3.0e38f;
        s_[m][a][1] = (cb + 1 < km[m][0]) ? s_[m][a][1] * SCALE_F : -3.0e38f;
        s_[m][a][2] = (cb     < km[m][1]) ? s_[m][a][2] * SCALE_F : -3.0e38f;
        s_[m][a][3] = (cb + 1 < km[m][1]) ? s_[m][a][3] * SCALE_F : -3.0e38f;
      }

    // ---- row max partials ----
    float pm[2][2];
#pragma unroll
    for (int m = 0; m < 2; m++) { pm[m][0] = -3.0e38f; pm[m][1] = -3.0e38f; }
#pragma unroll
    for (int m = 0; m < 2; m++)
#pragma unroll
      for (int a = 0; a < 4; a++) {
        pm[m][0] = fmaxf(pm[m][0], fmaxf(s_[m][a][0], s_[m][a][1]));
        pm[m][1] = fmaxf(pm[m][1], fmaxf(s_[m][a][2], s_[m][a][3]));
      }
#pragma unroll
    for (int m = 0; m < 2; m++)
#pragma unroll
      for (int hf = 0; hf < 2; hf++) {
        pm[m][hf] = fmaxf(pm[m][hf], __shfl_xor_sync(0xffffffffu, pm[m][hf], 1));
        pm[m][hf] = fmaxf(pm[m][hf], __shfl_xor_sync(0xffffffffu, pm[m][hf], 2));
      }
    if (t4 == 0) {
#pragma unroll
      for (int m = 0; m < 2; m++)
#pragma unroll
        for (int hf = 0; hf < 2; hf++)
          red_m[(r0l + 16 * m + 8 * hf) * 2 + wc] = pm[m][hf];
    }
    __syncthreads();   // K reads done; red_m visible

    // ---- V tile (overwrites K region; Vt [128 d][64 j] -> [128][72]) ----
#pragma unroll
    for (int i = 0; i < 8; i++) {
      int idx = t + 128 * i, d = idx >> 3, cq = (idx & 7) << 3;
      int jj = kb + cq;
      int sz = (jj < L_TOK) ? 16 : 0;
      if (jj >= L_TOK) jj = L_TOK - 8;
      unsigned dst = (unsigned)__cvta_generic_to_shared(KVs + d * 72 + cq);
      asm volatile("cp.async.cg.shared.global [%0], [%1], 16, %2;" ::"r"(dst),
                   "l"(vt + (size_t)(h * HD + d) * L_TOK + jj), "r"(sz));
    }
    asm volatile("cp.async.commit_group;");

    // ---- softmax, P -> smem fp16 ----
    float mnew[2][2], corr[2][2];
#pragma unroll
    for (int m = 0; m < 2; m++)
#pragma unroll
      for (int hf = 0; hf < 2; hf++) {
        int rl = r0l + 16 * m + 8 * hf;
        float mold = m_s[rl];
        float mn = fmaxf(mold, fmaxf(red_m[rl * 2], red_m[rl * 2 + 1]));
        mnew[m][hf] = mn;
        corr[m][hf] = __expf(mold - mn);
      }
    float pl[2][2] = {{0.f, 0.f}, {0.f, 0.f}};
#pragma unroll
    for (int m = 0; m < 2; m++) {
      int rl0 = r0l + 16 * m;
#pragma unroll
      for (int a = 0; a < 4; a++) {
        int cp = wc * 32 + a * 8 + 2 * t4;
        float e0 = __expf(s_[m][a][0] - mnew[m][0]);
        float e1 = __expf(s_[m][a][1] - mnew[m][0]);
        float e2 = __expf(s_[m][a][2] - mnew[m][1]);
        float e3 = __expf(s_[m][a][3] - mnew[m][1]);
        pl[m][0] += e0 + e1;
        pl[m][1] += e2 + e3;
        *(__half2*)(Ps + rl0 * 72 + cp) = __floats2half2_rn(e0, e1);
        *(__half2*)(Ps + (rl0 + 8) * 72 + cp) = __floats2half2_rn(e2, e3);
      }
    }
#pragma unroll
    for (int m = 0; m < 2; m++)
#pragma unroll
      for (int hf = 0; hf < 2; hf++) {
        pl[m][hf] += __shfl_xor_sync(0xffffffffu, pl[m][hf], 1);
        pl[m][hf] += __shfl_xor_sync(0xffffffffu, pl[m][hf], 2);
      }
    if (t4 == 0) {
#pragma unroll
      for (int m = 0; m < 2; m++)
#pragma unroll
        for (int hf = 0; hf < 2; hf++)
          red_l[(r0l + 16 * m + 8 * hf) * 2 + wc] = pl[m][hf];
    }
    __syncthreads();
    if (wc == 0 && t4 == 0) {
#pragma unroll
      for (int m = 0; m < 2; m++)
#pragma unroll
        for (int hf = 0; hf < 2; hf++) {
          int rl = r0l + 16 * m + 8 * hf;
          l_s[rl] = l_s[rl] * corr[m][hf] + red_l[rl * 2] + red_l[rl * 2 + 1];
          m_s[rl] = mnew[m][hf];
        }
    }
#pragma unroll
    for (int m = 0; m < 2; m++)
#pragma unroll
      for (int a = 0; a < 8; a++) {
        oa[m][a][0] *= corr[m][0]; oa[m][a][1] *= corr[m][0];
        oa[m][a][2] *= corr[m][1]; oa[m][a][3] *= corr[m][1];
      }
    asm volatile("cp.async.wait_group 0;");
    __syncthreads();   // V ready, Ps fully written

    // ---- O += P V ----
#pragma unroll
    for (int jk = 0; jk < 4; jk++) {
      const int kk = jk * 16;
      unsigned av[2][4], bv[4][4];
#pragma unroll
      for (int m = 0; m < 2; m++)
        ldsm4(av[m], ps_u + ((wr * 32 + 16 * m + ar) * 72 + kk + aklo) * 2);
#pragma unroll
      for (int bn = 0; bn < 4; bn++)
        ldsm4(bv[bn], kv_u + ((wc * 64 + 16 * bn + br) * 72 + kk + bklo) * 2);
#pragma unroll
      for (int m = 0; m < 2; m++)
#pragma unroll
        for (int a = 0; a < 8; a++)
          mma_f16(oa[m][a], av[m], (a & 1) ? (bv[a >> 1] + 2) : bv[a >> 1]);
    }
  }
  __syncthreads();

  // ---- epilogue: /l, fp16 store (feeds O-projection) ----
#pragma unroll
  for (int m = 0; m < 2; m++)
#pragma unroll
    for (int hf = 0; hf < 2; hf++) {
      int rl = r0l + 16 * m + 8 * hf;
      int grow = q0 + rl;
      if (grow < L_TOK) {
        float inv = 1.0f / l_s[rl];
#pragma unroll
        for (int a = 0; a < 8; a++) {
          int col = h * HD + wc * 64 + a * 8 + 2 * t4;
          *(__half2*)(o + (size_t)grow * DIM + col) =
              __floats2half2_rn(oa[m][a][hf * 2] * inv, oa[m][a][hf * 2 + 1] * inv);
        }
      }
    }
}

// ---------------- launch ----------------
extern "C" void kernel_launch(void* const* d_in, const int* in_sizes, int n_in,
                              void* d_out, int out_size) {
  const float* x  = (const float*)d_in[0];
  const float* wq = (const float*)d_in[1];
  const float* wk = (const float*)d_in[2];
  const float* wv = (const float*)d_in[3];
  const float* wo = (const float*)d_in[4];
  const float* bq = (const float*)d_in[5];
  const float* bk = (const float*)d_in[6];
  const float* bv = (const float*)d_in[7];
  const float* bo = (const float*)d_in[8];
  const float* gq = (const float*)d_in[9];
  const float* gk = (const float*)d_in[10];
  const float* fc = (const float*)d_in[11];
  const float* fs = (const float*)d_in[12];
  float* out = (float*)d_out;

  __half *qb, *kb, *vb, *ab, *xh, *wqkv, *wot;
  cudaGetSymbolAddress((void**)&qb, g_q);
  cudaGetSymbolAddress((void**)&kb, g_k);
  cudaGetSymbolAddress((void**)&vb, g_v);
  cudaGetSymbolAddress((void**)&ab, g_a);
  cudaGetSymbolAddress((void**)&xh, g_xh);
  cudaGetSymbolAddress((void**)&wqkv, g_wqkv);
  cudaGetSymbolAddress((void**)&wot, g_wo);

  cudaFuncSetAttribute(gemm_f16<1>, cudaFuncAttributeMaxDynamicSharedMemorySize, GEMM_SMEM);
  cudaFuncSetAttribute(gemm_f16<0>, cudaFuncAttributeMaxDynamicSharedMemorySize, GEMM_SMEM);
  cudaFuncSetAttribute(attn_f16_kernel, cudaFuncAttributeMaxDynamicSharedMemorySize, ATT_SMEM);

  int nx4 = L_TOK * DIM / 4;
  cvt_x_kernel<<<(nx4 + 255) / 256, 256>>>(x, xh, nx4);
  cvt_w_kernel<<<dim3(DIM / 32, DIM / 32, 4), dim3(32, 8)>>>(wq, wk, wv, wo, wqkv, wot);

  gemm_f16<1><<<dim3(3 * DIM / 128, (L_TOK + 127) / 128), 256, GEMM_SMEM>>>(
      xh, wqkv, bq, bk, bv, nullptr, qb, kb, vb, L_TOK);

  rms_rope_kernel<<<dim3(L_TOK, 2), 256>>>(qb, kb, gq, gk, fc, fs);

  attn_f16_kernel<<<dim3((L_TOK + 63) / 64, NH), 128, ATT_SMEM>>>(qb, kb, vb, ab);

  gemm_f16<0><<<dim3(DIM / 128, (L_TOK + 127) / 128), 256, GEMM_SMEM>>>(
      ab, wot, bo, nullptr, nullptr, out, nullptr, nullptr, nullptr, L_TOK);
}

// round 7
// speedup vs baseline: 1.9674x; 1.0053x over previous
#include <cuda_runtime.h>
#include <cuda_fp16.h>
#include <cstdint>

#define L_TOK 3120
#define DIM 1536
#define NH 12
#define HD 128
#define FR 1560
#define SCALE_F 0.08838834764831845f

// ---------------- scratch ----------------
__device__ __align__(16) __half g_q[L_TOK * DIM];       // Q fp16 (post rms_rope)
__device__ __align__(16) __half g_k[L_TOK * DIM];
__device__ __align__(16) __half g_v[L_TOK * DIM];       // V fp16, plain [L][DIM]
__device__ __align__(16) __half g_a[L_TOK * DIM];       // attn out fp16
__device__ __align__(16) __half g_xh[L_TOK * DIM];      // x fp16
__device__ __align__(16) __half g_wqkv[3 * DIM * DIM];  // [4608][1536] fp16 (W^T)
__device__ __align__(16) __half g_wo[DIM * DIM];        // wo^T fp16

// ---------------- helpers ----------------
__device__ __forceinline__ void mma_f16(float c[4], const unsigned a[4],
                                        const unsigned* b) {
  asm volatile(
      "mma.sync.aligned.m16n8k16.row.col.f32.f16.f16.f32 "
      "{%0,%1,%2,%3},{%4,%5,%6,%7},{%8,%9},{%0,%1,%2,%3};"
      : "+f"(c[0]), "+f"(c[1]), "+f"(c[2]), "+f"(c[3])
      : "r"(a[0]), "r"(a[1]), "r"(a[2]), "r"(a[3]), "r"(b[0]), "r"(b[1]));
}
__device__ __forceinline__ void ldsm4(unsigned r[4], uint32_t addr) {
  asm volatile(
      "ldmatrix.sync.aligned.m8n8.x4.shared.b16 {%0,%1,%2,%3}, [%4];"
      : "=r"(r[0]), "=r"(r[1]), "=r"(r[2]), "=r"(r[3]) : "r"(addr));
}
__device__ __forceinline__ void ldsm4t(unsigned r[4], uint32_t addr) {
  asm volatile(
      "ldmatrix.sync.aligned.m8n8.x4.trans.shared.b16 {%0,%1,%2,%3}, [%4];"
      : "=r"(r[0]), "=r"(r[1]), "=r"(r[2]), "=r"(r[3]) : "r"(addr));
}
__device__ __forceinline__ uint32_t smem_u32(const void* p) {
  uint32_t a;
  asm("{ .reg .u64 t; cvta.to.shared.u64 t, %1; cvt.u32.u64 %0, t; }"
      : "=r"(a) : "l"(p));
  return a;
}

// ---------------- cvt kernels ----------------
__global__ __launch_bounds__(256) void cvt_x_kernel(const float* __restrict__ s,
                                                    __half* __restrict__ d, int n4) {
  int i = blockIdx.x * 256 + threadIdx.x;
  if (i < n4) {
    float4 v = *(const float4*)(s + 4 * (size_t)i);
    __half2* dp = (__half2*)(d + 4 * (size_t)i);
    dp[0] = __floats2half2_rn(v.x, v.y);
    dp[1] = __floats2half2_rn(v.z, v.w);
  }
}

__global__ __launch_bounds__(256) void cvt_w_kernel(
    const float* __restrict__ w0, const float* __restrict__ w1,
    const float* __restrict__ w2, const float* __restrict__ w3,
    __half* __restrict__ qkv, __half* __restrict__ wot) {
  __shared__ float tile[32][33];
  const int z = blockIdx.z;
  const float* src = (z == 0) ? w0 : (z == 1) ? w1 : (z == 2) ? w2 : w3;
  __half* dst = (z == 3) ? wot : (qkv + (size_t)z * DIM * DIM);
  const int k0 = blockIdx.x * 32, n0 = blockIdx.y * 32;
  const int x = threadIdx.x, y = threadIdx.y;
#pragma unroll
  for (int i = 0; i < 4; i++)
    tile[y + 8 * i][x] = src[(size_t)(k0 + y + 8 * i) * DIM + n0 + x];
  __syncthreads();
#pragma unroll
  for (int i = 0; i < 4; i++)
    dst[(size_t)(n0 + y + 8 * i) * DIM + k0 + x] = __float2half(tile[x][y + 8 * i]);
}

// ---------------- fp16 GEMM: C[M][N] = A[M][K] @ Wt[N][K]^T ----------------
// CTA 64x256, BK=32, 256 thr (8 warps: 2m x 4n, warp 32x64). Wave-exact grids.
#define AST 40  // halfs; 80B stride -> conflict-free LDSM
#define A_HS (64 * AST)
#define B_HS (256 * AST)
#define GEMM_SMEM (2 * (A_HS + B_HS) * 2)

template <int QKV>
__global__ __launch_bounds__(256, 2) void gemm_f16(
    const __half* __restrict__ A, const __half* __restrict__ Wt,
    const float* __restrict__ b0, const float* __restrict__ b1,
    const float* __restrict__ b2, float* __restrict__ Cf,
    __half* __restrict__ H0, __half* __restrict__ H1,
    __half* __restrict__ H2, int M) {
  extern __shared__ __half smh[];
  __half* As = smh;                       // [2][64][40]
  __half* Bs = smh + 2 * A_HS;            // [2][256][40]
  const uint32_t as_u = smem_u32(As), bs_u = smem_u32(Bs);

  const int t = threadIdx.x;
  const int m0 = blockIdx.y * 64;
  const int n0g = blockIdx.x * 256;
  const int warp = t >> 5, lane = t & 31;
  const int wm = (warp & 1) * 32;
  const int wn = (warp >> 1) * 64;
  const int g = lane >> 2, t4 = lane & 3;
  const int ar = lane & 15, aklo = (lane & 16) >> 1;
  const int br = (lane & 7) + ((lane & 16) >> 1), bklo = lane & 8;

  float c[2][8][4];
#pragma unroll
  for (int i = 0; i < 2; i++)
#pragma unroll
    for (int j = 0; j < 8; j++)
#pragma unroll
      for (int r = 0; r < 4; r++) c[i][j][r] = 0.f;

  auto prefetch = [&](int buf, int k0) {
    __half* asb = As + buf * A_HS;
    __half* bsb = Bs + buf * B_HS;
    {
      int row = t >> 2, c8 = (t & 3) << 3;     // 256 chunks A
      int gr = m0 + row;
      if (gr >= M) gr = M - 1;
      unsigned dst = (unsigned)__cvta_generic_to_shared(asb + row * AST + c8);
      asm volatile("cp.async.cg.shared.global [%0], [%1], 16;" ::"r"(dst),
                   "l"(A + (size_t)gr * DIM + k0 + c8));
    }
#pragma unroll
    for (int i = 0; i < 4; i++) {
      int idx = t + 256 * i;                   // 1024 chunks B
      int row = idx >> 2, c8 = (idx & 3) << 3;
      unsigned dst = (unsigned)__cvta_generic_to_shared(bsb + row * AST + c8);
      asm volatile("cp.async.cg.shared.global [%0], [%1], 16;" ::"r"(dst),
                   "l"(Wt + (size_t)(n0g + row) * DIM + k0 + c8));
    }
  };

  prefetch(0, 0);
  asm volatile("cp.async.commit_group;");

  const int KT = DIM / 32;
  for (int kt = 0; kt < KT; kt++) {
    const int buf = kt & 1;
    if (kt + 1 < KT) prefetch(buf ^ 1, (kt + 1) * 32);
    asm volatile("cp.async.commit_group;");
    asm volatile("cp.async.wait_group 1;");
    __syncthreads();

    const uint32_t au = as_u + buf * A_HS * 2;
    const uint32_t bu = bs_u + buf * B_HS * 2;

#pragma unroll
    for (int kk = 0; kk < 32; kk += 16) {
      unsigned av[2][4], bv[4][4];
#pragma unroll
      for (int am = 0; am < 2; am++)
        ldsm4(av[am], au + ((wm + 16 * am - 16 * am + wm ? 0 : 0, (wm + 16 * am + ar)) * AST + kk + aklo) * 2);
#pragma unroll
      for (int bn = 0; bn < 4; bn++)
        ldsm4(bv[bn], bu + ((wn + 16 * bn + br) * AST + kk + bklo) * 2);
#pragma unroll
      for (int am = 0; am < 2; am++)
#pragma unroll
        for (int an = 0; an < 8; an++)
          mma_f16(c[am][an], av[am], (an & 1) ? (bv[an >> 1] + 2) : bv[an >> 1]);
    }
    __syncthreads();
  }

  // ---- epilogue ----
  int part = 0, ncol0 = n0g;
  const float* bias = b0;
  if (QKV) {
    part = n0g / DIM;
    ncol0 = n0g - part * DIM;
    bias = (part == 0) ? b0 : (part == 1) ? b1 : b2;
  }
  __half* H = QKV ? ((part == 0) ? H0 : (part == 1) ? H1 : H2) : (__half*)0;
#pragma unroll
  for (int am = 0; am < 2; am++) {
    const int r0 = m0 + wm + 16 * am + g;
    const int r1 = r0 + 8;
#pragma unroll
    for (int an = 0; an < 8; an++) {
      const int col = ncol0 + wn + 8 * an + 2 * t4;
      const float bb0 = bias[col], bb1 = bias[col + 1];
      if (!QKV) {
        if (r0 < M)
          *(float2*)(Cf + (size_t)r0 * DIM + col) =
              make_float2(c[am][an][0] + bb0, c[am][an][1] + bb1);
        if (r1 < M)
          *(float2*)(Cf + (size_t)r1 * DIM + col) =
              make_float2(c[am][an][2] + bb0, c[am][an][3] + bb1);
      } else {
        if (r0 < M)
          *(__half2*)(H + (size_t)r0 * DIM + col) =
              __floats2half2_rn(c[am][an][0] + bb0, c[am][an][1] + bb1);
        if (r1 < M)
          *(__half2*)(H + (size_t)r1 * DIM + col) =
              __floats2half2_rn(c[am][an][2] + bb0, c[am][an][3] + bb1);
      }
    }
  }
}

// ---------------- fused RMSNorm + RoPE (fp16 in/out) ----------------
__global__ __launch_bounds__(256) void rms_rope_kernel(
    __half* __restrict__ qbuf, __half* __restrict__ kbuf,
    const float* __restrict__ gq, const float* __restrict__ gk,
    const float* __restrict__ cosp, const float* __restrict__ sinp) {
  const int l = blockIdx.x;
  __half* row = (blockIdx.y == 0) ? (qbuf + (size_t)l * DIM) : (kbuf + (size_t)l * DIM);
  const float* g = (blockIdx.y == 0) ? gq : gk;
  const int t = threadIdx.x;

  float2 v[3];
  float ss = 0.f;
#pragma unroll
  for (int j = 0; j < 3; j++) {
    int p = t + 256 * j;
    v[j] = __half22float2(((const __half2*)row)[p]);
    ss += v[j].x * v[j].x + v[j].y * v[j].y;
  }
#pragma unroll
  for (int off = 16; off > 0; off >>= 1)
    ss += __shfl_xor_sync(0xffffffffu, ss, off);
  __shared__ float red[8];
  if ((t & 31) == 0) red[t >> 5] = ss;
  __syncthreads();
  float tot = 0.f;
#pragma unroll
  for (int w = 0; w < 8; w++) tot += red[w];
  const float r = rsqrtf(tot * (1.0f / (float)DIM) + 1e-6f);

#pragma unroll
  for (int j = 0; j < 3; j++) {
    int p = t + 256 * j;
    int hd2 = p & 63;
    float cth = cosp[l * 64 + hd2];
    float sth = sinp[l * 64 + hd2];
    float e = v[j].x * r * g[2 * p];
    float o = v[j].y * r * g[2 * p + 1];
    ((__half2*)row)[p] = __floats2half2_rn(e * cth - o * sth, e * sth + o * cth);
  }
}

// ---------------- fp16 tensor-core flash attention ----------------
// 128 thr = 4 warps 2x2. BQ=BKV=64. V plain layout + ldmatrix.trans.
#define QS_H (64 * 136)
#define KV_H (64 * 136)
#define PS_H (64 * 72)
#define ATT_SMEM ((QS_H + KV_H + PS_H) * 2 + (64 + 64 + 128 + 128) * 4)

__global__ __launch_bounds__(128, 2) void attn_f16_kernel(
    const __half* __restrict__ q, const __half* __restrict__ k,
    const __half* __restrict__ v, __half* __restrict__ o) {
  extern __shared__ __half smh[];
  __half* Qs = smh;
  __half* KVs = smh + QS_H;           // K tile, then reused for V tile (same layout)
  __half* Ps = KVs + KV_H;
  float* m_s = (float*)(Ps + PS_H);
  float* l_s = m_s + 64;
  float* red_m = l_s + 64;     // [64][2]
  float* red_l = red_m + 128;  // [64][2]
  const uint32_t qs_u = smem_u32(Qs), kv_u = smem_u32(KVs), ps_u = smem_u32(Ps);

  const int t = threadIdx.x, lane = t & 31, warp = t >> 5;
  const int g = lane >> 2, t4 = lane & 3;
  const int wr = warp & 1, wc = warp >> 1;
  // LPT: long (frame-1) query blocks dispatch first
  const int q0 = (gridDim.x - 1 - blockIdx.x) * 64;
  const int h = blockIdx.y;
  const int r0l = wr * 32 + g;
  const int ar = lane & 15, aklo = (lane & 16) >> 1;
  const int br = (lane & 7) + ((lane & 16) >> 1), bklo = lane & 8;
  const int vrow = lane & 15, vcol = (lane >> 4) << 3;   // trans-ldsm addressing

  // ---- Q tile: 64 rows x 128 halfs ----
#pragma unroll
  for (int i = 0; i < 8; i++) {
    int idx = t + 128 * i, r = idx >> 4, c8 = (idx & 15) << 3;
    int qr = q0 + r;
    int sz = (qr < L_TOK) ? 16 : 0;
    if (qr >= L_TOK) qr = L_TOK - 1;
    unsigned dst = (unsigned)__cvta_generic_to_shared(Qs + r * 136 + c8);
    asm volatile("cp.async.cg.shared.global [%0], [%1], 16, %2;" ::"r"(dst),
                 "l"(q + (size_t)qr * DIM + h * HD + c8), "r"(sz));
  }
  asm volatile("cp.async.commit_group;");
  if (t < 64) { m_s[t] = -3.0e38f; l_s[t] = 0.f; }

  float oa[2][8][4];
#pragma unroll
  for (int m = 0; m < 2; m++)
#pragma unroll
    for (int a = 0; a < 8; a++)
#pragma unroll
      for (int r = 0; r < 4; r++) oa[m][a][r] = 0.f;

  int km[2][2];
#pragma unroll
  for (int m = 0; m < 2; m++)
#pragma unroll
    for (int hf = 0; hf < 2; hf++) {
      int grow = q0 + r0l + 16 * m + 8 * hf;
      km[m][hf] = (grow < FR) ? FR : L_TOK;
    }

  int qlast = q0 + 63; if (qlast >= L_TOK) qlast = L_TOK - 1;
  const int ntiles = (((qlast < FR) ? FR : L_TOK) + 63) >> 6;

  for (int kt = 0; kt < ntiles; kt++) {
    const int kb = kt * 64;
    __syncthreads();                       // prior PV reads of KVs done
    // ---- K tile ----
#pragma unroll
    for (int i = 0; i < 8; i++) {
      int idx = t + 128 * i, r = idx >> 4, c8 = (idx & 15) << 3;
      int kr = kb + r;
      int sz = (kr < L_TOK) ? 16 : 0;
      if (kr >= L_TOK) kr = L_TOK - 1;
      unsigned dst = (unsigned)__cvta_generic_to_shared(KVs + r * 136 + c8);
      asm volatile("cp.async.cg.shared.global [%0], [%1], 16, %2;" ::"r"(dst),
                   "l"(k + (size_t)kr * DIM + h * HD + c8), "r"(sz));
    }
    asm volatile("cp.async.commit_group;");
    asm volatile("cp.async.wait_group 0;");
    __syncthreads();

    // ---- S = Q K^T ----
    float s_[2][4][4];
#pragma unroll
    for (int m = 0; m < 2; m++)
#pragma unroll
      for (int a = 0; a < 4; a++)
#pragma unroll
        for (int r = 0; r < 4; r++) s_[m][a][r] = 0.f;

#pragma unroll
    for (int k16 = 0; k16 < 8; k16++) {
      const int kk = k16 * 16;
      unsigned av[2][4], bv[2][4];
#pragma unroll
      for (int m = 0; m < 2; m++)
        ldsm4(av[m], qs_u + ((wr * 32 + 16 * m + ar) * 136 + kk + aklo) * 2);
#pragma unroll
      for (int bn = 0; bn < 2; bn++)
        ldsm4(bv[bn], kv_u + ((wc * 32 + 16 * bn + br) * 136 + kk + bklo) * 2);
#pragma unroll
      for (int m = 0; m < 2; m++)
#pragma unroll
        for (int a = 0; a < 4; a++)
          mma_f16(s_[m][a], av[m], (a & 1) ? (bv[a >> 1] + 2) : bv[a >> 1]);
    }

    // ---- scale + mask ----
#pragma unroll
    for (int m = 0; m < 2; m++)
#pragma unroll
      for (int a = 0; a < 4; a++) {
        int cb = kb + wc * 32 + a * 8 + 2 * t4;
        s_[m][a][0] = (cb     < km[m][0]) ? s_[m][a][0] * SCALE_F : -3.0e38f;
        s_[m][a][1] = (cb + 1 < km[m][0]) ? s_[m][a][1] * SCALE_F : -3.0e38f;
        s_[m][a][2] = (cb     < km[m][1]) ? s_[m][a][2] * SCALE_F : -3.0e38f;
        s_[m][a][3] = (cb + 1 < km[m][1]) ? s_[m][a][3] * SCALE_F : -3.0e38f;
      }

    // ---- row max partials ----
    float pm[2][2];
#pragma unroll
    for (int m = 0; m < 2; m++) { pm[m][0] = -3.0e38f; pm[m][1] = -3.0e38f; }
#pragma unroll
    for (int m = 0; m < 2; m++)
#pragma unroll
      for (int a = 0; a < 4; a++) {
        pm[m][0] = fmaxf(pm[m][0], fmaxf(s_[m][a][0], s_[m][a][1]));
        pm[m][1] = fmaxf(pm[m][1], fmaxf(s_[m][a][2], s_[m][a][3]));
      }
#pragma unroll
    for (int m = 0; m < 2; m++)
#pragma unroll
      for (int hf = 0; hf < 2; hf++) {
        pm[m][hf] = fmaxf(pm[m][hf], __shfl_xor_sync(0xffffffffu, pm[m][hf], 1));
        pm[m][hf] = fmaxf(pm[m][hf], __shfl_xor_sync(0xffffffffu, pm[m][hf], 2));
      }
    if (t4 == 0) {
#pragma unroll
      for (int m = 0; m < 2; m++)
#pragma unroll
        for (int hf = 0; hf < 2; hf++)
          red_m[(r0l + 16 * m + 8 * hf) * 2 + wc] = pm[m][hf];
    }
    __syncthreads();   // K reads done; red_m visible

    // ---- V tile (plain [j][d] rows, overwrites K region) ----
#pragma unroll
    for (int i = 0; i < 8; i++) {
      int idx = t + 128 * i, r = idx >> 4, c8 = (idx & 15) << 3;
      int kr = kb + r;
      int sz = (kr < L_TOK) ? 16 : 0;
      if (kr >= L_TOK) kr = L_TOK - 1;
      unsigned dst = (unsigned)__cvta_generic_to_shared(KVs + r * 136 + c8);
      asm volatile("cp.async.cg.shared.global [%0], [%1], 16, %2;" ::"r"(dst),
                   "l"(v + (size_t)kr * DIM + h * HD + c8), "r"(sz));
    }
    asm volatile("cp.async.commit_group;");

    // ---- softmax, P -> smem fp16 ----
    float mnew[2][2], corr[2][2];
#pragma unroll
    for (int m = 0; m < 2; m++)
#pragma unroll
      for (int hf = 0; hf < 2; hf++) {
        int rl = r0l + 16 * m + 8 * hf;
        float mold = m_s[rl];
        float mn = fmaxf(mold, fmaxf(red_m[rl * 2], red_m[rl * 2 + 1]));
        mnew[m][hf] = mn;
        corr[m][hf] = __expf(mold - mn);
      }
    float pl[2][2] = {{0.f, 0.f}, {0.f, 0.f}};
#pragma unroll
    for (int m = 0; m < 2; m++) {
      int rl0 = r0l + 16 * m;
#pragma unroll
      for (int a = 0; a < 4; a++) {
        int cp = wc * 32 + a * 8 + 2 * t4;
        float e0 = __expf(s_[m][a][0] - mnew[m][0]);
        float e1 = __expf(s_[m][a][1] - mnew[m][0]);
        float e2 = __expf(s_[m][a][2] - mnew[m][1]);
        float e3 = __expf(s_[m][a][3] - mnew[m][1]);
        pl[m][0] += e0 + e1;
        pl[m][1] += e2 + e3;
        *(__half2*)(Ps + rl0 * 72 + cp) = __floats2half2_rn(e0, e1);
        *(__half2*)(Ps + (rl0 + 8) * 72 + cp) = __floats2half2_rn(e2, e3);
      }
    }
#pragma unroll
    for (int m = 0; m < 2; m++)
#pragma unroll
      for (int hf = 0; hf < 2; hf++) {
        pl[m][hf] += __shfl_xor_sync(0xffffffffu, pl[m][hf], 1);
        pl[m][hf] += __shfl_xor_sync(0xffffffffu, pl[m][hf], 2);
      }
    if (t4 == 0) {
#pragma unroll
      for (int m = 0; m < 2; m++)
#pragma unroll
        for (int hf = 0; hf < 2; hf++)
          red_l[(r0l + 16 * m + 8 * hf) * 2 + wc] = pl[m][hf];
    }
    __syncthreads();
    if (wc == 0 && t4 == 0) {
#pragma unroll
      for (int m = 0; m < 2; m++)
#pragma unroll
        for (int hf = 0; hf < 2; hf++) {
          int rl = r0l + 16 * m + 8 * hf;
          l_s[rl] = l_s[rl] * corr[m][hf] + red_l[rl * 2] + red_l[rl * 2 + 1];
          m_s[rl] = mnew[m][hf];
        }
    }
#pragma unroll
    for (int m = 0; m < 2; m++)
#pragma unroll
      for (int a = 0; a < 8; a++) {
        oa[m][a][0] *= corr[m][0]; oa[m][a][1] *= corr[m][0];
        oa[m][a][2] *= corr[m][1]; oa[m][a][3] *= corr[m][1];
      }
    asm volatile("cp.async.wait_group 0;");
    __syncthreads();   // V ready, Ps fully written

    // ---- O += P V (V via ldmatrix.trans from [j][d]) ----
#pragma unroll
    for (int jk = 0; jk < 4; jk++) {
      const int kk = jk * 16;
      unsigned av[2][4], bv[4][4];
#pragma unroll
      for (int m = 0; m < 2; m++)
        ldsm4(av[m], ps_u + ((wr * 32 + 16 * m + ar) * 72 + kk + aklo) * 2);
#pragma unroll
      for (int bn = 0; bn < 4; bn++)
        ldsm4t(bv[bn],
               kv_u + ((kk + vrow) * 136 + wc * 64 + 16 * bn + vcol) * 2);
#pragma unroll
      for (int m = 0; m < 2; m++)
#pragma unroll
        for (int a = 0; a < 8; a++)
          mma_f16(oa[m][a], av[m], (a & 1) ? (bv[a >> 1] + 2) : bv[a >> 1]);
    }
  }
  __syncthreads();

  // ---- epilogue: /l, fp16 store (feeds O-projection) ----
#pragma unroll
  for (int m = 0; m < 2; m++)
#pragma unroll
    for (int hf = 0; hf < 2; hf++) {
      int rl = r0l + 16 * m + 8 * hf;
      int grow = q0 + rl;
      if (grow < L_TOK) {
        float inv = 1.0f / l_s[rl];
#pragma unroll
        for (int a = 0; a < 8; a++) {
          int col = h * HD + wc * 64 + a * 8 + 2 * t4;
          *(__half2*)(o + (size_t)grow * DIM + col) =
              __floats2half2_rn(oa[m][a][hf * 2] * inv, oa[m][a][hf * 2 + 1] * inv);
        }
      }
    }
}

// ---------------- launch ----------------
extern "C" void kernel_launch(void* const* d_in, const int* in_sizes, int n_in,
                              void* d_out, int out_size) {
  const float* x  = (const float*)d_in[0];
  const float* wq = (const float*)d_in[1];
  const float* wk = (const float*)d_in[2];
  const float* wv = (const float*)d_in[3];
  const float* wo = (const float*)d_in[4];
  const float* bq = (const float*)d_in[5];
  const float* bk = (const float*)d_in[6];
  const float* bv = (const float*)d_in[7];
  const float* bo = (const float*)d_in[8];
  const float* gq = (const float*)d_in[9];
  const float* gk = (const float*)d_in[10];
  const float* fc = (const float*)d_in[11];
  const float* fs = (const float*)d_in[12];
  float* out = (float*)d_out;

  __half *qb, *kb, *vb, *ab, *xh, *wqkv, *wot;
  cudaGetSymbolAddress((void**)&qb, g_q);
  cudaGetSymbolAddress((void**)&kb, g_k);
  cudaGetSymbolAddress((void**)&vb, g_v);
  cudaGetSymbolAddress((void**)&ab, g_a);
  cudaGetSymbolAddress((void**)&xh, g_xh);
  cudaGetSymbolAddress((void**)&wqkv, g_wqkv);
  cudaGetSymbolAddress((void**)&wot, g_wo);

  cudaFuncSetAttribute(gemm_f16<1>, cudaFuncAttributeMaxDynamicSharedMemorySize, GEMM_SMEM);
  cudaFuncSetAttribute(gemm_f16<0>, cudaFuncAttributeMaxDynamicSharedMemorySize, GEMM_SMEM);
  cudaFuncSetAttribute(attn_f16_kernel, cudaFuncAttributeMaxDynamicSharedMemorySize, ATT_SMEM);

  int nx4 = L_TOK * DIM / 4;
  cvt_x_kernel<<<(nx4 + 255) / 256, 256>>>(x, xh, nx4);
  cvt_w_kernel<<<dim3(DIM / 32, DIM / 32, 4), dim3(32, 8)>>>(wq, wk, wv, wo, wqkv, wot);

  // QKV: 18 x 49 = 882 CTAs (2.98 waves at occ 2)
  gemm_f16<1><<<dim3(3 * DIM / 256, (L_TOK + 63) / 64), 256, GEMM_SMEM>>>(
      xh, wqkv, bq, bk, bv, nullptr, qb, kb, vb, L_TOK);

  rms_rope_kernel<<<dim3(L_TOK, 2), 256>>>(qb, kb, gq, gk, fc, fs);

  // attention: 49 x 12 = 588 CTAs (~2 waves at occ 2), LPT via block reversal
  attn_f16_kernel<<<dim3((L_TOK + 63) / 64, NH), 128, ATT_SMEM>>>(qb, kb, vb, ab);

  // O-proj: 6 x 49 = 294 CTAs (exactly one wave at occ 2)
  gemm_f16<0><<<dim3(DIM / 256, (L_TOK + 63) / 64), 256, GEMM_SMEM>>>(
      ab, wot, bo, nullptr, nullptr, out, nullptr, nullptr, nullptr, L_TOK);
}

// round 8
// speedup vs baseline: 2.2573x; 1.1474x over previous
#include <cuda_runtime.h>
#include <cuda_fp16.h>
#include <cstdint>

#define L_TOK 3120
#define DIM 1536
#define NH 12
#define HD 128
#define FR 1560
#define SCALE_F 0.08838834764831845f

// ---------------- scratch ----------------
__device__ __align__(16) __half g_q[L_TOK * DIM];       // Q fp16 (post rms_rope)
__device__ __align__(16) __half g_k[L_TOK * DIM];
__device__ __align__(16) __half g_v[L_TOK * DIM];       // V fp16, plain [L][DIM]
__device__ __align__(16) __half g_a[L_TOK * DIM];       // attn out fp16
__device__ __align__(16) __half g_xh[L_TOK * DIM];      // x fp16
__device__ __align__(16) __half g_wqkv[3 * DIM * DIM];  // [4608][1536] fp16 (W^T)
__device__ __align__(16) __half g_wo[DIM * DIM];        // wo^T fp16

// ---------------- helpers ----------------
__device__ __forceinline__ void mma_f16(float c[4], const unsigned a[4],
                                        const unsigned* b) {
  asm volatile(
      "mma.sync.aligned.m16n8k16.row.col.f32.f16.f16.f32 "
      "{%0,%1,%2,%3},{%4,%5,%6,%7},{%8,%9},{%0,%1,%2,%3};"
      : "+f"(c[0]), "+f"(c[1]), "+f"(c[2]), "+f"(c[3])
      : "r"(a[0]), "r"(a[1]), "r"(a[2]), "r"(a[3]), "r"(b[0]), "r"(b[1]));
}
__device__ __forceinline__ void ldsm4(unsigned r[4], uint32_t addr) {
  asm volatile(
      "ldmatrix.sync.aligned.m8n8.x4.shared.b16 {%0,%1,%2,%3}, [%4];"
      : "=r"(r[0]), "=r"(r[1]), "=r"(r[2]), "=r"(r[3]) : "r"(addr));
}
__device__ __forceinline__ void ldsm4t(unsigned r[4], uint32_t addr) {
  asm volatile(
      "ldmatrix.sync.aligned.m8n8.x4.trans.shared.b16 {%0,%1,%2,%3}, [%4];"
      : "=r"(r[0]), "=r"(r[1]), "=r"(r[2]), "=r"(r[3]) : "r"(addr));
}
__device__ __forceinline__ uint32_t smem_u32(const void* p) {
  uint32_t a;
  asm("{ .reg .u64 t; cvta.to.shared.u64 t, %1; cvt.u32.u64 %0, t; }"
      : "=r"(a) : "l"(p));
  return a;
}
__device__ __forceinline__ unsigned h2u(float a, float b) {
  __half2 h = __floats2half2_rn(a, b);
  return *(unsigned*)&h;
}

// ---------------- cvt kernels ----------------
__global__ __launch_bounds__(256) void cvt_x_kernel(const float* __restrict__ s,
                                                    __half* __restrict__ d, int n4) {
  int i = blockIdx.x * 256 + threadIdx.x;
  if (i < n4) {
    float4 v = *(const float4*)(s + 4 * (size_t)i);
    __half2* dp = (__half2*)(d + 4 * (size_t)i);
    dp[0] = __floats2half2_rn(v.x, v.y);
    dp[1] = __floats2half2_rn(v.z, v.w);
  }
}

__global__ __launch_bounds__(256) void cvt_w_kernel(
    const float* __restrict__ w0, const float* __restrict__ w1,
    const float* __restrict__ w2, const float* __restrict__ w3,
    __half* __restrict__ qkv, __half* __restrict__ wot) {
  __shared__ float tile[32][33];
  const int z = blockIdx.z;
  const float* src = (z == 0) ? w0 : (z == 1) ? w1 : (z == 2) ? w2 : w3;
  __half* dst = (z == 3) ? wot : (qkv + (size_t)z * DIM * DIM);
  const int k0 = blockIdx.x * 32, n0 = blockIdx.y * 32;
  const int x = threadIdx.x, y = threadIdx.y;
#pragma unroll
  for (int i = 0; i < 4; i++)
    tile[y + 8 * i][x] = src[(size_t)(k0 + y + 8 * i) * DIM + n0 + x];
  __syncthreads();
#pragma unroll
  for (int i = 0; i < 4; i++)
    dst[(size_t)(n0 + y + 8 * i) * DIM + k0 + x] = __float2half(tile[x][y + 8 * i]);
}

// ---------------- fp16 GEMM: C[M][N] = A[M][K] @ Wt[N][K]^T ----------------
// CTA 64x256, BK=32, 256 thr (8 warps: 2m x 4n, warp 32x64). 3-stage cp.async.
#define AST 40
#define A_HS (64 * AST)
#define B_HS (256 * AST)
#define NST 3
#define GEMM_SMEM (NST * (A_HS + B_HS) * 2)

template <int QKV>
__global__ __launch_bounds__(256, 2) void gemm_f16(
    const __half* __restrict__ A, const __half* __restrict__ Wt,
    const float* __restrict__ b0, const float* __restrict__ b1,
    const float* __restrict__ b2, float* __restrict__ Cf,
    __half* __restrict__ H0, __half* __restrict__ H1,
    __half* __restrict__ H2, int M) {
  extern __shared__ __half smh[];
  const uint32_t sm_u = smem_u32(smh);

  const int t = threadIdx.x;
  const int m0 = blockIdx.y * 64;
  const int n0g = blockIdx.x * 256;
  const int warp = t >> 5, lane = t & 31;
  const int wm = (warp & 1) * 32;
  const int wn = (warp >> 1) * 64;
  const int g = lane >> 2, t4 = lane & 3;
  const int ar = lane & 15, aklo = (lane & 16) >> 1;
  const int br = (lane & 7) + ((lane & 16) >> 1), bklo = lane & 8;

  float c[2][8][4];
#pragma unroll
  for (int i = 0; i < 2; i++)
#pragma unroll
    for (int j = 0; j < 8; j++)
#pragma unroll
      for (int r = 0; r < 4; r++) c[i][j][r] = 0.f;

  auto prefetch = [&](int buf, int k0) {
    __half* asb = smh + buf * (A_HS + B_HS);
    __half* bsb = asb + A_HS;
    {
      int row = t >> 2, c8 = (t & 3) << 3;
      int gr = m0 + row;
      if (gr >= M) gr = M - 1;
      unsigned dst = (unsigned)__cvta_generic_to_shared(asb + row * AST + c8);
      asm volatile("cp.async.cg.shared.global [%0], [%1], 16;" ::"r"(dst),
                   "l"(A + (size_t)gr * DIM + k0 + c8));
    }
#pragma unroll
    for (int i = 0; i < 4; i++) {
      int idx = t + 256 * i;
      int row = idx >> 2, c8 = (idx & 3) << 3;
      unsigned dst = (unsigned)__cvta_generic_to_shared(bsb + row * AST + c8);
      asm volatile("cp.async.cg.shared.global [%0], [%1], 16;" ::"r"(dst),
                   "l"(Wt + (size_t)(n0g + row) * DIM + k0 + c8));
    }
  };

  prefetch(0, 0);
  asm volatile("cp.async.commit_group;");
  prefetch(1, 32);
  asm volatile("cp.async.commit_group;");

  const int KT = DIM / 32;
  for (int kt = 0; kt < KT; kt++) {
    const int s = kt % 3;
    if (kt + 2 < KT) prefetch((kt + 2) % 3, (kt + 2) * 32);
    asm volatile("cp.async.commit_group;");      // one commit per iter, may be empty
    asm volatile("cp.async.wait_group 2;");
    __syncthreads();

    const uint32_t au = sm_u + s * (A_HS + B_HS) * 2;
    const uint32_t bu = au + A_HS * 2;

#pragma unroll
    for (int kk = 0; kk < 32; kk += 16) {
      unsigned av[2][4], bv[4][4];
#pragma unroll
      for (int am = 0; am < 2; am++)
        ldsm4(av[am], au + ((wm + 16 * am + ar) * AST + kk + aklo) * 2);
#pragma unroll
      for (int bn = 0; bn < 4; bn++)
        ldsm4(bv[bn], bu + ((wn + 16 * bn + br) * AST + kk + bklo) * 2);
#pragma unroll
      for (int am = 0; am < 2; am++)
#pragma unroll
        for (int an = 0; an < 8; an++)
          mma_f16(c[am][an], av[am], (an & 1) ? (bv[an >> 1] + 2) : bv[an >> 1]);
    }
    __syncthreads();
  }

  // ---- epilogue ----
  int part = 0, ncol0 = n0g;
  const float* bias = b0;
  if (QKV) {
    part = n0g / DIM;
    ncol0 = n0g - part * DIM;
    bias = (part == 0) ? b0 : (part == 1) ? b1 : b2;
  }
  __half* H = QKV ? ((part == 0) ? H0 : (part == 1) ? H1 : H2) : (__half*)0;
#pragma unroll
  for (int am = 0; am < 2; am++) {
    const int r0 = m0 + wm + 16 * am + g;
    const int r1 = r0 + 8;
#pragma unroll
    for (int an = 0; an < 8; an++) {
      const int col = ncol0 + wn + 8 * an + 2 * t4;
      const float bb0 = bias[col], bb1 = bias[col + 1];
      if (!QKV) {
        if (r0 < M)
          *(float2*)(Cf + (size_t)r0 * DIM + col) =
              make_float2(c[am][an][0] + bb0, c[am][an][1] + bb1);
        if (r1 < M)
          *(float2*)(Cf + (size_t)r1 * DIM + col) =
              make_float2(c[am][an][2] + bb0, c[am][an][3] + bb1);
      } else {
        if (r0 < M)
          *(__half2*)(H + (size_t)r0 * DIM + col) =
              __floats2half2_rn(c[am][an][0] + bb0, c[am][an][1] + bb1);
        if (r1 < M)
          *(__half2*)(H + (size_t)r1 * DIM + col) =
              __floats2half2_rn(c[am][an][2] + bb0, c[am][an][3] + bb1);
      }
    }
  }
}

// ---------------- fused RMSNorm + RoPE (fp16 in/out) ----------------
__global__ __launch_bounds__(256) void rms_rope_kernel(
    __half* __restrict__ qbuf, __half* __restrict__ kbuf,
    const float* __restrict__ gq, const float* __restrict__ gk,
    const float* __restrict__ cosp, const float* __restrict__ sinp) {
  const int l = blockIdx.x;
  __half* row = (blockIdx.y == 0) ? (qbuf + (size_t)l * DIM) : (kbuf + (size_t)l * DIM);
  const float* g = (blockIdx.y == 0) ? gq : gk;
  const int t = threadIdx.x;

  float2 v[3];
  float ss = 0.f;
#pragma unroll
  for (int j = 0; j < 3; j++) {
    int p = t + 256 * j;
    v[j] = __half22float2(((const __half2*)row)[p]);
    ss += v[j].x * v[j].x + v[j].y * v[j].y;
  }
#pragma unroll
  for (int off = 16; off > 0; off >>= 1)
    ss += __shfl_xor_sync(0xffffffffu, ss, off);
  __shared__ float red[8];
  if ((t & 31) == 0) red[t >> 5] = ss;
  __syncthreads();
  float tot = 0.f;
#pragma unroll
  for (int w = 0; w < 8; w++) tot += red[w];
  const float r = rsqrtf(tot * (1.0f / (float)DIM) + 1e-6f);

#pragma unroll
  for (int j = 0; j < 3; j++) {
    int p = t + 256 * j;
    int hd2 = p & 63;
    float cth = cosp[l * 64 + hd2];
    float sth = sinp[l * 64 + hd2];
    float e = v[j].x * r * g[2 * p];
    float o = v[j].y * r * g[2 * p + 1];
    ((__half2*)row)[p] = __floats2half2_rn(e * cth - o * sth, e * sth + o * cth);
  }
}

// ---------------- fp16 flash attention, warp-local softmax (FA2 style) -----
// 128 thr = 4 warps x 16 query rows each. K double-buffered, V single buffer,
// P kept in registers (C-frag of S == A-frag of PV). 2 syncs per KV tile.
#define TILE_H (64 * 136)
#define ATT_SMEM (4 * TILE_H * 2)   // Q + K0 + K1 + V

__global__ __launch_bounds__(128, 2) void attn_f16_kernel(
    const __half* __restrict__ q, const __half* __restrict__ k,
    const __half* __restrict__ v, __half* __restrict__ o) {
  extern __shared__ __half smh[];
  __half* Qs = smh;
  const uint32_t qs_u = smem_u32(Qs);
  const uint32_t k0_u = qs_u + TILE_H * 2;
  const uint32_t k1_u = k0_u + TILE_H * 2;
  const uint32_t vb_u = k1_u + TILE_H * 2;

  const int t = threadIdx.x, lane = t & 31, w = t >> 5;
  const int g = lane >> 2, t4 = lane & 3;
  const int q0 = (int)(gridDim.x - 1 - blockIdx.x) * 64;   // LPT: long blocks first
  const int h = blockIdx.y;
  const int rw = w * 16;
  const int ar = lane & 15, aklo = (lane & 16) >> 1;
  const int br = (lane & 7) + ((lane & 16) >> 1), bklo = lane & 8;
  const int vrow = lane & 15, vcol = (lane >> 4) << 3;

  auto load_tile = [&](const __half* src, uint32_t dst_u, int kb) {
#pragma unroll
    for (int i = 0; i < 8; i++) {
      int idx = t + 128 * i, r = idx >> 4, c8 = (idx & 15) << 3;
      int kr = kb + r;
      int sz = (kr < L_TOK) ? 16 : 0;
      if (kr >= L_TOK) kr = L_TOK - 1;
      asm volatile("cp.async.cg.shared.global [%0], [%1], 16, %2;" ::
                   "r"(dst_u + (uint32_t)(r * 136 + c8) * 2),
                   "l"(src + (size_t)kr * DIM + h * HD + c8), "r"(sz));
    }
  };

  // prologue: Q + K(0) in one group
  load_tile(q, qs_u, q0);
  load_tile(k, k0_u, 0);
  asm volatile("cp.async.commit_group;");

  float oa[16][4];
#pragma unroll
  for (int a = 0; a < 16; a++)
#pragma unroll
    for (int r = 0; r < 4; r++) oa[a][r] = 0.f;

  float m0 = -3.0e38f, m1 = -3.0e38f, l0 = 0.f, l1 = 0.f;
  const int km0 = (q0 + rw + g < FR) ? FR : L_TOK;
  const int km1 = (q0 + rw + 8 + g < FR) ? FR : L_TOK;

  int qlast = q0 + 63; if (qlast >= L_TOK) qlast = L_TOK - 1;
  const int nt = (((qlast < FR) ? FR : L_TOK) + 63) >> 6;

  for (int kt = 0; kt < nt; kt++) {
    const int kb = kt * 64;
    const uint32_t ku = (kt & 1) ? k1_u : k0_u;
    asm volatile("cp.async.wait_group 0;");   // K(kt) (and Q on kt=0) complete
    __syncthreads();                          // visibility + V/K buffer safety

    load_tile(v, vb_u, kb);
    asm volatile("cp.async.commit_group;");
    const bool pk = (kt + 1 < nt);
    if (pk) {
      load_tile(k, ((kt + 1) & 1) ? k1_u : k0_u, kb + 64);
      asm volatile("cp.async.commit_group;");
    }

    // ---- S = Q K^T : warp tile 16 rows x 64 cols (8 n-atoms) ----
    float s_[8][4];
#pragma unroll
    for (int a = 0; a < 8; a++)
#pragma unroll
      for (int r = 0; r < 4; r++) s_[a][r] = 0.f;

#pragma unroll
    for (int k16 = 0; k16 < 8; k16++) {
      const int kk = k16 * 16;
      unsigned av[4], bv[4][4];
      ldsm4(av, qs_u + ((rw + ar) * 136 + kk + aklo) * 2);
#pragma unroll
      for (int bn = 0; bn < 4; bn++)
        ldsm4(bv[bn], ku + ((16 * bn + br) * 136 + kk + bklo) * 2);
#pragma unroll
      for (int a = 0; a < 8; a++)
        mma_f16(s_[a], av, (a & 1) ? (bv[a >> 1] + 2) : bv[a >> 1]);
    }

    // ---- scale + mask ----
#pragma unroll
    for (int a = 0; a < 8; a++) {
      int cb = kb + 8 * a + 2 * t4;
      s_[a][0] = (cb     < km0) ? s_[a][0] * SCALE_F : -3.0e38f;
      s_[a][1] = (cb + 1 < km0) ? s_[a][1] * SCALE_F : -3.0e38f;
      s_[a][2] = (cb     < km1) ? s_[a][2] * SCALE_F : -3.0e38f;
      s_[a][3] = (cb + 1 < km1) ? s_[a][3] * SCALE_F : -3.0e38f;
    }

    // ---- warp-local softmax (quad shuffles only) ----
    float mx0 = -3.0e38f, mx1 = -3.0e38f;
#pragma unroll
    for (int a = 0; a < 8; a++) {
      mx0 = fmaxf(mx0, fmaxf(s_[a][0], s_[a][1]));
      mx1 = fmaxf(mx1, fmaxf(s_[a][2], s_[a][3]));
    }
    mx0 = fmaxf(mx0, __shfl_xor_sync(0xffffffffu, mx0, 1));
    mx0 = fmaxf(mx0, __shfl_xor_sync(0xffffffffu, mx0, 2));
    mx1 = fmaxf(mx1, __shfl_xor_sync(0xffffffffu, mx1, 1));
    mx1 = fmaxf(mx1, __shfl_xor_sync(0xffffffffu, mx1, 2));
    const float mn0 = fmaxf(m0, mx0), mn1 = fmaxf(m1, mx1);
    const float cr0 = __expf(m0 - mn0), cr1 = __expf(m1 - mn1);
    m0 = mn0; m1 = mn1;

    unsigned pa[4][4];   // P as A-fragments (4 k16 groups)
    float sl0 = 0.f, sl1 = 0.f;
#pragma unroll
    for (int jk = 0; jk < 4; jk++) {
#pragma unroll
      for (int hh = 0; hh < 2; hh++) {
        const int a = 2 * jk + hh;
        float e0 = __expf(s_[a][0] - mn0);
        float e1 = __expf(s_[a][1] - mn0);
        float e2 = __expf(s_[a][2] - mn1);
        float e3 = __expf(s_[a][3] - mn1);
        sl0 += e0 + e1; sl1 += e2 + e3;
        pa[jk][2 * hh] = h2u(e0, e1);
        pa[jk][2 * hh + 1] = h2u(e2, e3);
      }
    }
    sl0 += __shfl_xor_sync(0xffffffffu, sl0, 1);
    sl0 += __shfl_xor_sync(0xffffffffu, sl0, 2);
    sl1 += __shfl_xor_sync(0xffffffffu, sl1, 1);
    sl1 += __shfl_xor_sync(0xffffffffu, sl1, 2);
    l0 = l0 * cr0 + sl0;
    l1 = l1 * cr1 + sl1;

#pragma unroll
    for (int a = 0; a < 16; a++) {
      oa[a][0] *= cr0; oa[a][1] *= cr0;
      oa[a][2] *= cr1; oa[a][3] *= cr1;
    }

    if (pk) asm volatile("cp.async.wait_group 1;");   // V done (K(kt+1) pending)
    else    asm volatile("cp.async.wait_group 0;");
    __syncthreads();                                  // V visible to all warps

    // ---- O += P V : V via ldmatrix.trans, P from registers ----
#pragma unroll
    for (int jk = 0; jk < 4; jk++) {
      const int kk = jk * 16;
      unsigned bv[8][4];
#pragma unroll
      for (int nb = 0; nb < 8; nb++)
        ldsm4t(bv[nb], vb_u + ((kk + vrow) * 136 + 16 * nb + vcol) * 2);
#pragma unroll
      for (int na = 0; na < 16; na++)
        mma_f16(oa[na], pa[jk], (na & 1) ? (bv[na >> 1] + 2) : bv[na >> 1]);
    }
  }

  // ---- epilogue: /l, fp16 store ----
  const float inv0 = 1.0f / l0, inv1 = 1.0f / l1;
  const int gr0 = q0 + rw + g, gr1 = gr0 + 8;
#pragma unroll
  for (int na = 0; na < 16; na++) {
    const int col = h * HD + 8 * na + 2 * t4;
    if (gr0 < L_TOK)
      *(__half2*)(o + (size_t)gr0 * DIM + col) =
          __floats2half2_rn(oa[na][0] * inv0, oa[na][1] * inv0);
    if (gr1 < L_TOK)
      *(__half2*)(o + (size_t)gr1 * DIM + col) =
          __floats2half2_rn(oa[na][2] * inv1, oa[na][3] * inv1);
  }
}

// ---------------- launch ----------------
extern "C" void kernel_launch(void* const* d_in, const int* in_sizes, int n_in,
                              void* d_out, int out_size) {
  const float* x  = (const float*)d_in[0];
  const float* wq = (const float*)d_in[1];
  const float* wk = (const float*)d_in[2];
  const float* wv = (const float*)d_in[3];
  const float* wo = (const float*)d_in[4];
  const float* bq = (const float*)d_in[5];
  const float* bk = (const float*)d_in[6];
  const float* bv = (const float*)d_in[7];
  const float* bo = (const float*)d_in[8];
  const float* gq = (const float*)d_in[9];
  const float* gk = (const float*)d_in[10];
  const float* fc = (const float*)d_in[11];
  const float* fs = (const float*)d_in[12];
  float* out = (float*)d_out;

  __half *qb, *kb, *vb, *ab, *xh, *wqkv, *wot;
  cudaGetSymbolAddress((void**)&qb, g_q);
  cudaGetSymbolAddress((void**)&kb, g_k);
  cudaGetSymbolAddress((void**)&vb, g_v);
  cudaGetSymbolAddress((void**)&ab, g_a);
  cudaGetSymbolAddress((void**)&xh, g_xh);
  cudaGetSymbolAddress((void**)&wqkv, g_wqkv);
  cudaGetSymbolAddress((void**)&wot, g_wo);

  cudaFuncSetAttribute(gemm_f16<1>, cudaFuncAttributeMaxDynamicSharedMemorySize, GEMM_SMEM);
  cudaFuncSetAttribute(gemm_f16<0>, cudaFuncAttributeMaxDynamicSharedMemorySize, GEMM_SMEM);
  cudaFuncSetAttribute(attn_f16_kernel, cudaFuncAttributeMaxDynamicSharedMemorySize, ATT_SMEM);

  int nx4 = L_TOK * DIM / 4;
  cvt_x_kernel<<<(nx4 + 255) / 256, 256>>>(x, xh, nx4);
  cvt_w_kernel<<<dim3(DIM / 32, DIM / 32, 4), dim3(32, 8)>>>(wq, wk, wv, wo, wqkv, wot);

  gemm_f16<1><<<dim3(3 * DIM / 256, (L_TOK + 63) / 64), 256, GEMM_SMEM>>>(
      xh, wqkv, bq, bk, bv, nullptr, qb, kb, vb, L_TOK);

  rms_rope_kernel<<<dim3(L_TOK, 2), 256>>>(qb, kb, gq, gk, fc, fs);

  attn_f16_kernel<<<dim3((L_TOK + 63) / 64, NH), 128, ATT_SMEM>>>(qb, kb, vb, ab);

  gemm_f16<0><<<dim3(DIM / 256, (L_TOK + 63) / 64), 256, GEMM_SMEM>>>(
      ab, wot, bo, nullptr, nullptr, out, nullptr, nullptr, nullptr, L_TOK);
}

// round 9
// speedup vs baseline: 2.2924x; 1.0155x over previous
#include <cuda_runtime.h>
#include <cuda_fp16.h>
#include <cstdint>

#define L_TOK 3120
#define DIM 1536
#define NH 12
#define HD 128
#define FR 1560
#define SCALE_F 0.08838834764831845f

// ---------------- scratch ----------------
__device__ __align__(16) __half g_q[L_TOK * DIM];       // Q fp16 (post rms_rope)
__device__ __align__(16) __half g_k[L_TOK * DIM];
__device__ __align__(16) __half g_v[L_TOK * DIM];       // V fp16, plain [L][DIM]
__device__ __align__(16) __half g_a[L_TOK * DIM];       // attn out fp16
__device__ __align__(16) __half g_xh[L_TOK * DIM];      // x fp16
__device__ __align__(16) __half g_wqkv[3 * DIM * DIM];  // [4608][1536] fp16 (W^T)
__device__ __align__(16) __half g_wo[DIM * DIM];        // wo^T fp16

// ---------------- helpers ----------------
__device__ __forceinline__ void mma_f16(float c[4], const unsigned a[4],
                                        const unsigned* b) {
  asm volatile(
      "mma.sync.aligned.m16n8k16.row.col.f32.f16.f16.f32 "
      "{%0,%1,%2,%3},{%4,%5,%6,%7},{%8,%9},{%0,%1,%2,%3};"
      : "+f"(c[0]), "+f"(c[1]), "+f"(c[2]), "+f"(c[3])
      : "r"(a[0]), "r"(a[1]), "r"(a[2]), "r"(a[3]), "r"(b[0]), "r"(b[1]));
}
__device__ __forceinline__ void ldsm4(unsigned r[4], uint32_t addr) {
  asm volatile(
      "ldmatrix.sync.aligned.m8n8.x4.shared.b16 {%0,%1,%2,%3}, [%4];"
      : "=r"(r[0]), "=r"(r[1]), "=r"(r[2]), "=r"(r[3]) : "r"(addr));
}
__device__ __forceinline__ void ldsm4t(unsigned r[4], uint32_t addr) {
  asm volatile(
      "ldmatrix.sync.aligned.m8n8.x4.trans.shared.b16 {%0,%1,%2,%3}, [%4];"
      : "=r"(r[0]), "=r"(r[1]), "=r"(r[2]), "=r"(r[3]) : "r"(addr));
}
__device__ __forceinline__ uint32_t smem_u32(const void* p) {
  uint32_t a;
  asm("{ .reg .u64 t; cvta.to.shared.u64 t, %1; cvt.u32.u64 %0, t; }"
      : "=r"(a) : "l"(p));
  return a;
}
__device__ __forceinline__ unsigned h2u(float a, float b) {
  __half2 h = __floats2half2_rn(a, b);
  return *(unsigned*)&h;
}

// ---------------- cvt kernels ----------------
__global__ __launch_bounds__(256) void cvt_x_kernel(const float* __restrict__ s,
                                                    __half* __restrict__ d, int n4) {
  int i = blockIdx.x * 256 + threadIdx.x;
  if (i < n4) {
    float4 v = *(const float4*)(s + 4 * (size_t)i);
    __half2* dp = (__half2*)(d + 4 * (size_t)i);
    dp[0] = __floats2half2_rn(v.x, v.y);
    dp[1] = __floats2half2_rn(v.z, v.w);
  }
}

__global__ __launch_bounds__(256) void cvt_w_kernel(
    const float* __restrict__ w0, const float* __restrict__ w1,
    const float* __restrict__ w2, const float* __restrict__ w3,
    __half* __restrict__ qkv, __half* __restrict__ wot) {
  __shared__ float tile[32][33];
  const int z = blockIdx.z;
  const float* src = (z == 0) ? w0 : (z == 1) ? w1 : (z == 2) ? w2 : w3;
  __half* dst = (z == 3) ? wot : (qkv + (size_t)z * DIM * DIM);
  const int k0 = blockIdx.x * 32, n0 = blockIdx.y * 32;
  const int x = threadIdx.x, y = threadIdx.y;
#pragma unroll
  for (int i = 0; i < 4; i++)
    tile[y + 8 * i][x] = src[(size_t)(k0 + y + 8 * i) * DIM + n0 + x];
  __syncthreads();
#pragma unroll
  for (int i = 0; i < 4; i++)
    dst[(size_t)(n0 + y + 8 * i) * DIM + k0 + x] = __float2half(tile[x][y + 8 * i]);
}

// ---------------- fp16 GEMM: C[M][N] = A[M][K] @ Wt[N][K]^T ----------------
// CTA 64x256, BK=32, 256 thr (8 warps: 2m x 4n, warp 32x64).
// 3-stage cp.async, ONE __syncthreads per mainloop iter.
#define AST 40
#define A_HS (64 * AST)
#define B_HS (256 * AST)
#define NST 3
#define GEMM_SMEM (NST * (A_HS + B_HS) * 2)

template <int QKV>
__global__ __launch_bounds__(256, 2) void gemm_f16(
    const __half* __restrict__ A, const __half* __restrict__ Wt,
    const float* __restrict__ b0, const float* __restrict__ b1,
    const float* __restrict__ b2, float* __restrict__ Cf,
    __half* __restrict__ H0, __half* __restrict__ H1,
    __half* __restrict__ H2, int M) {
  extern __shared__ __half smh[];
  const uint32_t sm_u = smem_u32(smh);

  const int t = threadIdx.x;
  const int m0 = blockIdx.y * 64;
  const int n0g = blockIdx.x * 256;
  const int warp = t >> 5, lane = t & 31;
  const int wm = (warp & 1) * 32;
  const int wn = (warp >> 1) * 64;
  const int g = lane >> 2, t4 = lane & 3;
  const int ar = lane & 15, aklo = (lane & 16) >> 1;
  const int br = (lane & 7) + ((lane & 16) >> 1), bklo = lane & 8;

  float c[2][8][4];
#pragma unroll
  for (int i = 0; i < 2; i++)
#pragma unroll
    for (int j = 0; j < 8; j++)
#pragma unroll
      for (int r = 0; r < 4; r++) c[i][j][r] = 0.f;

  auto prefetch = [&](int buf, int k0) {
    __half* asb = smh + buf * (A_HS + B_HS);
    __half* bsb = asb + A_HS;
    {
      int row = t >> 2, c8 = (t & 3) << 3;
      int gr = m0 + row;
      if (gr >= M) gr = M - 1;
      unsigned dst = (unsigned)__cvta_generic_to_shared(asb + row * AST + c8);
      asm volatile("cp.async.cg.shared.global [%0], [%1], 16;" ::"r"(dst),
                   "l"(A + (size_t)gr * DIM + k0 + c8));
    }
#pragma unroll
    for (int i = 0; i < 4; i++) {
      int idx = t + 256 * i;
      int row = idx >> 2, c8 = (idx & 3) << 3;
      unsigned dst = (unsigned)__cvta_generic_to_shared(bsb + row * AST + c8);
      asm volatile("cp.async.cg.shared.global [%0], [%1], 16;" ::"r"(dst),
                   "l"(Wt + (size_t)(n0g + row) * DIM + k0 + c8));
    }
  };

  prefetch(0, 0);
  asm volatile("cp.async.commit_group;");
  prefetch(1, 32);
  asm volatile("cp.async.commit_group;");

  const int KT = DIM / 32;
  for (int kt = 0; kt < KT; kt++) {
    const int s = kt % 3;
    asm volatile("cp.async.wait_group 1;");   // stage kt resident
    __syncthreads();                          // all warps past mma(kt-1), data visible

    const uint32_t au = sm_u + s * (A_HS + B_HS) * 2;
    const uint32_t bu = au + A_HS * 2;

#pragma unroll
    for (int kk = 0; kk < 32; kk += 16) {
      unsigned av[2][4], bv[4][4];
#pragma unroll
      for (int am = 0; am < 2; am++)
        ldsm4(av[am], au + ((wm + 16 * am + ar) * AST + kk + aklo) * 2);
#pragma unroll
      for (int bn = 0; bn < 4; bn++)
        ldsm4(bv[bn], bu + ((wn + 16 * bn + br) * AST + kk + bklo) * 2);
#pragma unroll
      for (int am = 0; am < 2; am++)
#pragma unroll
        for (int an = 0; an < 8; an++)
          mma_f16(c[am][an], av[am], (an & 1) ? (bv[an >> 1] + 2) : bv[an >> 1]);
    }

    if (kt + 2 < KT) prefetch((kt + 2) % 3, (kt + 2) * 32);
    asm volatile("cp.async.commit_group;");   // one commit per iter (may be empty)
  }

  // ---- epilogue ----
  int part = 0, ncol0 = n0g;
  const float* bias = b0;
  if (QKV) {
    part = n0g / DIM;
    ncol0 = n0g - part * DIM;
    bias = (part == 0) ? b0 : (part == 1) ? b1 : b2;
  }
  __half* H = QKV ? ((part == 0) ? H0 : (part == 1) ? H1 : H2) : (__half*)0;
#pragma unroll
  for (int am = 0; am < 2; am++) {
    const int r0 = m0 + wm + 16 * am + g;
    const int r1 = r0 + 8;
#pragma unroll
    for (int an = 0; an < 8; an++) {
      const int col = ncol0 + wn + 8 * an + 2 * t4;
      const float bb0 = bias[col], bb1 = bias[col + 1];
      if (!QKV) {
        if (r0 < M)
          *(float2*)(Cf + (size_t)r0 * DIM + col) =
              make_float2(c[am][an][0] + bb0, c[am][an][1] + bb1);
        if (r1 < M)
          *(float2*)(Cf + (size_t)r1 * DIM + col) =
              make_float2(c[am][an][2] + bb0, c[am][an][3] + bb1);
      } else {
        if (r0 < M)
          *(__half2*)(H + (size_t)r0 * DIM + col) =
              __floats2half2_rn(c[am][an][0] + bb0, c[am][an][1] + bb1);
        if (r1 < M)
          *(__half2*)(H + (size_t)r1 * DIM + col) =
              __floats2half2_rn(c[am][an][2] + bb0, c[am][an][3] + bb1);
      }
    }
  }
}

// ---------------- fused RMSNorm + RoPE (fp16 in/out), 512 thr ----------------
__global__ __launch_bounds__(512) void rms_rope_kernel(
    __half* __restrict__ qbuf, __half* __restrict__ kbuf,
    const float* __restrict__ gq, const float* __restrict__ gk,
    const float* __restrict__ cosp, const float* __restrict__ sinp) {
  const int l = blockIdx.x;
  const int half = threadIdx.x >> 8;          // 0 -> q, 1 -> k
  __half* row = (half == 0) ? (qbuf + (size_t)l * DIM) : (kbuf + (size_t)l * DIM);
  const float* g = (half == 0) ? gq : gk;
  const int t = threadIdx.x & 255;

  float2 v[3];
  float ss = 0.f;
#pragma unroll
  for (int j = 0; j < 3; j++) {
    int p = t + 256 * j;
    v[j] = __half22float2(((const __half2*)row)[p]);
    ss += v[j].x * v[j].x + v[j].y * v[j].y;
  }
#pragma unroll
  for (int off = 16; off > 0; off >>= 1)
    ss += __shfl_xor_sync(0xffffffffu, ss, off);
  __shared__ float red[2][8];
  if ((t & 31) == 0) red[half][t >> 5] = ss;
  __syncthreads();
  float tot = 0.f;
#pragma unroll
  for (int w = 0; w < 8; w++) tot += red[half][w];
  const float r = rsqrtf(tot * (1.0f / (float)DIM) + 1e-6f);

#pragma unroll
  for (int j = 0; j < 3; j++) {
    int p = t + 256 * j;
    int hd2 = p & 63;
    float cth = cosp[l * 64 + hd2];
    float sth = sinp[l * 64 + hd2];
    float e = v[j].x * r * g[2 * p];
    float o = v[j].y * r * g[2 * p + 1];
    ((__half2*)row)[p] = __floats2half2_rn(e * cth - o * sth, e * sth + o * cth);
  }
}

// ---------------- fp16 flash attention, warp-local softmax, occ 3 ----------
#define TILE_H (64 * 136)
#define ATT_SMEM (4 * TILE_H * 2)   // Q + K0 + K1 + V  (68 KB)

__global__ __launch_bounds__(128, 3) void attn_f16_kernel(
    const __half* __restrict__ q, const __half* __restrict__ k,
    const __half* __restrict__ v, __half* __restrict__ o) {
  extern __shared__ __half smh[];
  __half* Qs = smh;
  const uint32_t qs_u = smem_u32(Qs);
  const uint32_t k0_u = qs_u + TILE_H * 2;
  const uint32_t k1_u = k0_u + TILE_H * 2;
  const uint32_t vb_u = k1_u + TILE_H * 2;

  const int t = threadIdx.x, lane = t & 31, w = t >> 5;
  const int g = lane >> 2, t4 = lane & 3;
  const int q0 = (int)(gridDim.x - 1 - blockIdx.x) * 64;   // LPT: long blocks first
  const int h = blockIdx.y;
  const int rw = w * 16;
  const int ar = lane & 15, aklo = (lane & 16) >> 1;
  const int br = (lane & 7) + ((lane & 16) >> 1), bklo = lane & 8;
  const int vrow = lane & 15, vcol = (lane >> 4) << 3;

  auto load_tile = [&](const __half* src, uint32_t dst_u, int kb) {
#pragma unroll
    for (int i = 0; i < 8; i++) {
      int idx = t + 128 * i, r = idx >> 4, c8 = (idx & 15) << 3;
      int kr = kb + r;
      int sz = (kr < L_TOK) ? 16 : 0;
      if (kr >= L_TOK) kr = L_TOK - 1;
      asm volatile("cp.async.cg.shared.global [%0], [%1], 16, %2;" ::
                   "r"(dst_u + (uint32_t)(r * 136 + c8) * 2),
                   "l"(src + (size_t)kr * DIM + h * HD + c8), "r"(sz));
    }
  };

  load_tile(q, qs_u, q0);
  load_tile(k, k0_u, 0);
  asm volatile("cp.async.commit_group;");

  float oa[16][4];
#pragma unroll
  for (int a = 0; a < 16; a++)
#pragma unroll
    for (int r = 0; r < 4; r++) oa[a][r] = 0.f;

  float m0 = -3.0e38f, m1 = -3.0e38f, l0 = 0.f, l1 = 0.f;
  const int km0 = (q0 + rw + g < FR) ? FR : L_TOK;
  const int km1 = (q0 + rw + 8 + g < FR) ? FR : L_TOK;

  int qlast = q0 + 63; if (qlast >= L_TOK) qlast = L_TOK - 1;
  const int nt = (((qlast < FR) ? FR : L_TOK) + 63) >> 6;

  for (int kt = 0; kt < nt; kt++) {
    const int kb = kt * 64;
    const uint32_t ku = (kt & 1) ? k1_u : k0_u;
    asm volatile("cp.async.wait_group 0;");
    __syncthreads();

    load_tile(v, vb_u, kb);
    asm volatile("cp.async.commit_group;");
    const bool pk = (kt + 1 < nt);
    if (pk) {
      load_tile(k, ((kt + 1) & 1) ? k1_u : k0_u, kb + 64);
      asm volatile("cp.async.commit_group;");
    }

    // ---- S = Q K^T ----
    float s_[8][4];
#pragma unroll
    for (int a = 0; a < 8; a++)
#pragma unroll
      for (int r = 0; r < 4; r++) s_[a][r] = 0.f;

#pragma unroll
    for (int k16 = 0; k16 < 8; k16++) {
      const int kk = k16 * 16;
      unsigned av[4], bv[4][4];
      ldsm4(av, qs_u + ((rw + ar) * 136 + kk + aklo) * 2);
#pragma unroll
      for (int bn = 0; bn < 4; bn++)
        ldsm4(bv[bn], ku + ((16 * bn + br) * 136 + kk + bklo) * 2);
#pragma unroll
      for (int a = 0; a < 8; a++)
        mma_f16(s_[a], av, (a & 1) ? (bv[a >> 1] + 2) : bv[a >> 1]);
    }

    // ---- scale + mask ----
#pragma unroll
    for (int a = 0; a < 8; a++) {
      int cb = kb + 8 * a + 2 * t4;
      s_[a][0] = (cb     < km0) ? s_[a][0] * SCALE_F : -3.0e38f;
      s_[a][1] = (cb + 1 < km0) ? s_[a][1] * SCALE_F : -3.0e38f;
      s_[a][2] = (cb     < km1) ? s_[a][2] * SCALE_F : -3.0e38f;
      s_[a][3] = (cb + 1 < km1) ? s_[a][3] * SCALE_F : -3.0e38f;
    }

    // ---- warp-local softmax ----
    float mx0 = -3.0e38f, mx1 = -3.0e38f;
#pragma unroll
    for (int a = 0; a < 8; a++) {
      mx0 = fmaxf(mx0, fmaxf(s_[a][0], s_[a][1]));
      mx1 = fmaxf(mx1, fmaxf(s_[a][2], s_[a][3]));
    }
    mx0 = fmaxf(mx0, __shfl_xor_sync(0xffffffffu, mx0, 1));
    mx0 = fmaxf(mx0, __shfl_xor_sync(0xffffffffu, mx0, 2));
    mx1 = fmaxf(mx1, __shfl_xor_sync(0xffffffffu, mx1, 1));
    mx1 = fmaxf(mx1, __shfl_xor_sync(0xffffffffu, mx1, 2));
    const float mn0 = fmaxf(m0, mx0), mn1 = fmaxf(m1, mx1);
    const float cr0 = __expf(m0 - mn0), cr1 = __expf(m1 - mn1);
    m0 = mn0; m1 = mn1;

    unsigned pa[4][4];
    float sl0 = 0.f, sl1 = 0.f;
#pragma unroll
    for (int jk = 0; jk < 4; jk++) {
#pragma unroll
      for (int hh = 0; hh < 2; hh++) {
        const int a = 2 * jk + hh;
        float e0 = __expf(s_[a][0] - mn0);
        float e1 = __expf(s_[a][1] - mn0);
        float e2 = __expf(s_[a][2] - mn1);
        float e3 = __expf(s_[a][3] - mn1);
        sl0 += e0 + e1; sl1 += e2 + e3;
        pa[jk][2 * hh] = h2u(e0, e1);
        pa[jk][2 * hh + 1] = h2u(e2, e3);
      }
    }
    sl0 += __shfl_xor_sync(0xffffffffu, sl0, 1);
    sl0 += __shfl_xor_sync(0xffffffffu, sl0, 2);
    sl1 += __shfl_xor_sync(0xffffffffu, sl1, 1);
    sl1 += __shfl_xor_sync(0xffffffffu, sl1, 2);
    l0 = l0 * cr0 + sl0;
    l1 = l1 * cr1 + sl1;

#pragma unroll
    for (int a = 0; a < 16; a++) {
      oa[a][0] *= cr0; oa[a][1] *= cr0;
      oa[a][2] *= cr1; oa[a][3] *= cr1;
    }

    if (pk) asm volatile("cp.async.wait_group 1;");
    else    asm volatile("cp.async.wait_group 0;");
    __syncthreads();

    // ---- O += P V ----
#pragma unroll
    for (int jk = 0; jk < 4; jk++) {
      const int kk = jk * 16;
      unsigned bv[8][4];
#pragma unroll
      for (int nb = 0; nb < 8; nb++)
        ldsm4t(bv[nb], vb_u + ((kk + vrow) * 136 + 16 * nb + vcol) * 2);
#pragma unroll
      for (int na = 0; na < 16; na++)
        mma_f16(oa[na], pa[jk], (na & 1) ? (bv[na >> 1] + 2) : bv[na >> 1]);
    }
  }

  // ---- epilogue ----
  const float inv0 = 1.0f / l0, inv1 = 1.0f / l1;
  const int gr0 = q0 + rw + g, gr1 = gr0 + 8;
#pragma unroll
  for (int na = 0; na < 16; na++) {
    const int col = h * HD + 8 * na + 2 * t4;
    if (gr0 < L_TOK)
      *(__half2*)(o + (size_t)gr0 * DIM + col) =
          __floats2half2_rn(oa[na][0] * inv0, oa[na][1] * inv0);
    if (gr1 < L_TOK)
      *(__half2*)(o + (size_t)gr1 * DIM + col) =
          __floats2half2_rn(oa[na][2] * inv1, oa[na][3] * inv1);
  }
}

// ---------------- launch ----------------
extern "C" void kernel_launch(void* const* d_in, const int* in_sizes, int n_in,
                              void* d_out, int out_size) {
  const float* x  = (const float*)d_in[0];
  const float* wq = (const float*)d_in[1];
  const float* wk = (const float*)d_in[2];
  const float* wv = (const float*)d_in[3];
  const float* wo = (const float*)d_in[4];
  const float* bq = (const float*)d_in[5];
  const float* bk = (const float*)d_in[6];
  const float* bv = (const float*)d_in[7];
  const float* bo = (const float*)d_in[8];
  const float* gq = (const float*)d_in[9];
  const float* gk = (const float*)d_in[10];
  const float* fc = (const float*)d_in[11];
  const float* fs = (const float*)d_in[12];
  float* out = (float*)d_out;

  __half *qb, *kb, *vb, *ab, *xh, *wqkv, *wot;
  cudaGetSymbolAddress((void**)&qb, g_q);
  cudaGetSymbolAddress((void**)&kb, g_k);
  cudaGetSymbolAddress((void**)&vb, g_v);
  cudaGetSymbolAddress((void**)&ab, g_a);
  cudaGetSymbolAddress((void**)&xh, g_xh);
  cudaGetSymbolAddress((void**)&wqkv, g_wqkv);
  cudaGetSymbolAddress((void**)&wot, g_wo);

  cudaFuncSetAttribute(gemm_f16<1>, cudaFuncAttributeMaxDynamicSharedMemorySize, GEMM_SMEM);
  cudaFuncSetAttribute(gemm_f16<0>, cudaFuncAttributeMaxDynamicSharedMemorySize, GEMM_SMEM);
  cudaFuncSetAttribute(attn_f16_kernel, cudaFuncAttributeMaxDynamicSharedMemorySize, ATT_SMEM);

  int nx4 = L_TOK * DIM / 4;
  cvt_x_kernel<<<(nx4 + 255) / 256, 256>>>(x, xh, nx4);
  cvt_w_kernel<<<dim3(DIM / 32, DIM / 32, 4), dim3(32, 8)>>>(wq, wk, wv, wo, wqkv, wot);

  gemm_f16<1><<<dim3(3 * DIM / 256, (L_TOK + 63) / 64), 256, GEMM_SMEM>>>(
      xh, wqkv, bq, bk, bv, nullptr, qb, kb, vb, L_TOK);

  rms_rope_kernel<<<L_TOK, 512>>>(qb, kb, gq, gk, fc, fs);

  attn_f16_kernel<<<dim3((L_TOK + 63) / 64, NH), 128, ATT_SMEM>>>(qb, kb, vb, ab);

  gemm_f16<0><<<dim3(DIM / 256, (L_TOK + 63) / 64), 256, GEMM_SMEM>>>(
      ab, wot, bo, nullptr, nullptr, out, nullptr, nullptr, nullptr, L_TOK);
}